// round 1
// baseline (speedup 1.0000x reference)
#include <cuda_runtime.h>
#include <math.h>

// Problem dims
#define NB 2048
#define ND 1024
#define NH 1024
#define NZ 256
#define NE 64

// ---------------- scratch (static device globals; no allocation) ----------------
__device__ __align__(16) float g_hcat[NB * (NZ + NH + ND)];   // [B, 2304]
__device__ __align__(16) float g_cat2[NB * (NH + ND)];        // [B, 2048]
__device__ __align__(16) float g_hg[NB * 4 * NZ];             // [B, 1024]
__device__ __align__(16) float g_z[NB * 3 * 4 * NE];          // [B, 768] = [z_h|z_x|z_b]
__device__ __align__(16) float g_dyh[NB * 4 * NH];            // [B, 4096]
__device__ __align__(16) float g_dyx[NB * 4 * NH];
__device__ __align__(16) float g_dyb[NB * 4 * NH];
__device__ __align__(16) float g_gates[NB * 4 * NH];

__device__ __forceinline__ float sigf(float v) { return 1.f / (1.f + __expf(-v)); }

// ---------------- input concatenation: hcat=[hhat0|h0|x], cat2=[h0|x] ----------------
__global__ void concat_kernel(const float4* __restrict__ x,
                              const float4* __restrict__ h0,
                              const float4* __restrict__ hhat0) {
    float4* hc = reinterpret_cast<float4*>(g_hcat);
    float4* c2 = reinterpret_cast<float4*>(g_cat2);
    const int HC4 = (NZ + NH + ND) / 4;  // 576 float4 per row
    const int N1 = NB * HC4;
    const int stride = gridDim.x * blockDim.x;
    for (int i = blockIdx.x * blockDim.x + threadIdx.x; i < N1; i += stride) {
        int b = i / HC4;
        int c = i - b * HC4;
        float4 v;
        if (c < NZ / 4)                 v = hhat0[b * (NZ / 4) + c];
        else if (c < (NZ + NH) / 4)     v = h0[b * (NH / 4) + (c - NZ / 4)];
        else                            v = x[b * (ND / 4) + (c - (NZ + NH) / 4)];
        hc[i] = v;
    }
    const int N2 = NB * 512;  // 512 float4 per cat2 row
    for (int i = blockIdx.x * blockDim.x + threadIdx.x; i < N2; i += stride) {
        int b = i >> 9;
        int c = i & 511;
        c2[i] = (c < 256) ? h0[b * 256 + c] : x[b * 256 + (c - 256)];
    }
}

// ---------------- generic 128x128 fp32 GEMM, BK=16, 256 thr, 8x8/thread ----------------
// C[row,col] = sum_k A[row,k]*B[k,col]   (+ optional modulation epilogue, + optional bias)
// Requires: grid exactly tiles M,N; K % 16 == 0; all pointers 16B-aligned; lda/ldb % 4 == 0.
__global__ __launch_bounds__(256, 2)
void sgemm128(const float* __restrict__ A, const float* __restrict__ Bw,
              float* __restrict__ C,
              int K, int lda, int ldb, int ldc,
              const float* __restrict__ bias,
              const float* __restrict__ dyh,
              const float* __restrict__ dyx,
              const float* __restrict__ dyb) {
    __shared__ float As[16][132];   // transposed, padded vs bank conflicts
    __shared__ float Bs[16][128];

    const int tid = threadIdx.x;
    const int tr = tid >> 4;      // 0..15
    const int tc = tid & 15;      // 0..15
    const int bM = blockIdx.y * 128;
    const int bN = blockIdx.x * 128;

    const float* Ap = A + (size_t)bM * lda;
    const float* Bp = Bw + bN;

    float acc[8][8] = {};

    const int aRow = tid >> 2;          // 0..63
    const int aCol = (tid & 3) << 2;    // 0,4,8,12
    const int bRow = tid >> 5;          // 0..7
    const int bCol = (tid & 31) << 2;   // 0..124

    for (int k0 = 0; k0 < K; k0 += 16) {
#pragma unroll
        for (int r = 0; r < 2; r++) {
            int row = aRow + r * 64;
            float4 v = *reinterpret_cast<const float4*>(Ap + (size_t)row * lda + k0 + aCol);
            As[aCol + 0][row] = v.x;
            As[aCol + 1][row] = v.y;
            As[aCol + 2][row] = v.z;
            As[aCol + 3][row] = v.w;
        }
#pragma unroll
        for (int r = 0; r < 2; r++) {
            int row = bRow + r * 8;
            *reinterpret_cast<float4*>(&Bs[row][bCol]) =
                *reinterpret_cast<const float4*>(Bp + (size_t)(k0 + row) * ldb + bCol);
        }
        __syncthreads();
#pragma unroll
        for (int k = 0; k < 16; k++) {
            float ra[8], rb[8];
#pragma unroll
            for (int i = 0; i < 8; i++) ra[i] = As[k][tr * 8 + i];
#pragma unroll
            for (int j = 0; j < 8; j++) rb[j] = Bs[k][tc * 8 + j];
#pragma unroll
            for (int i = 0; i < 8; i++)
#pragma unroll
                for (int j = 0; j < 8; j++)
                    acc[i][j] = fmaf(ra[i], rb[j], acc[i][j]);
        }
        __syncthreads();
    }

#pragma unroll
    for (int i = 0; i < 8; i++) {
        int row = bM + tr * 8 + i;
#pragma unroll
        for (int j = 0; j < 8; j++) {
            int col = bN + tc * 8 + j;
            size_t off = (size_t)row * ldc + col;
            float v = acc[i][j];
            if (dyh) v = v * dyh[off] * dyx[off] + dyb[off];
            if (bias) v += bias[col];
            C[off] = v;
        }
    }
}

// ---------------- hyper LSTM elementwise ----------------
__global__ void hyper_cell(const float* __restrict__ chat0,
                           float* __restrict__ out_hhat1,
                           float* __restrict__ out_chat1) {
    int idx = blockIdx.x * blockDim.x + threadIdx.x;
    if (idx >= NB * NZ) return;
    int b = idx >> 8;
    int z = idx & (NZ - 1);
    const float* row = g_hg + (size_t)b * (4 * NZ);
    float iv = row[z], gv = row[NZ + z], fv = row[2 * NZ + z], ov = row[3 * NZ + z];
    float c1 = sigf(fv) * chat0[idx] + sigf(iv) * tanhf(gv);
    out_chat1[idx] = c1;
    out_hhat1[idx] = sigf(ov) * tanhf(c1);
}

// ---------------- main LSTM elementwise ----------------
__global__ void main_cell(const float* __restrict__ c0,
                          float* __restrict__ out_h1,
                          float* __restrict__ out_c1) {
    int idx = blockIdx.x * blockDim.x + threadIdx.x;
    if (idx >= NB * NH) return;
    int b = idx >> 10;
    int h = idx & (NH - 1);
    const float* row = g_gates + (size_t)b * (4 * NH);
    float iv = row[h], gv = row[NH + h], fv = row[2 * NH + h], ov = row[3 * NH + h];
    float c1 = sigf(fv) * c0[idx] + sigf(iv) * tanhf(gv);
    out_c1[idx] = c1;
    out_h1[idx] = sigf(ov) * tanhf(c1);
}

// ---------------- launch ----------------
extern "C" void kernel_launch(void* const* d_in, const int* in_sizes, int n_in,
                              void* d_out, int out_size) {
    const float* x       = (const float*)d_in[0];
    const float* h0      = (const float*)d_in[1];
    const float* c0      = (const float*)d_in[2];
    // d_in[3] = hhat0, d_in[4] = chat0
    const float* hhat0   = (const float*)d_in[3];
    const float* chat0   = (const float*)d_in[4];
    const float* hweight = (const float*)d_in[5];
    const float* hbias   = (const float*)d_in[6];
    const float* zw_h    = (const float*)d_in[7];
    const float* zw_x    = (const float*)d_in[8];
    const float* zw_b    = (const float*)d_in[9];
    const float* zb_h    = (const float*)d_in[10];
    const float* zb_x    = (const float*)d_in[11];
    const float* dw_h    = (const float*)d_in[12];
    const float* dw_x    = (const float*)d_in[13];
    const float* dw_b    = (const float*)d_in[14];
    const float* weight  = (const float*)d_in[15];
    const float* bias    = (const float*)d_in[16];
    float* out = (float*)d_out;

    float *p_hcat, *p_cat2, *p_hg, *p_z, *p_dyh, *p_dyx, *p_dyb, *p_gates;
    cudaGetSymbolAddress((void**)&p_hcat, g_hcat);
    cudaGetSymbolAddress((void**)&p_cat2, g_cat2);
    cudaGetSymbolAddress((void**)&p_hg, g_hg);
    cudaGetSymbolAddress((void**)&p_z, g_z);
    cudaGetSymbolAddress((void**)&p_dyh, g_dyh);
    cudaGetSymbolAddress((void**)&p_dyx, g_dyx);
    cudaGetSymbolAddress((void**)&p_dyb, g_dyb);
    cudaGetSymbolAddress((void**)&p_gates, g_gates);

    float* out_h1    = out;
    float* out_c1    = out + (size_t)NB * NH;
    float* out_hhat1 = out + (size_t)2 * NB * NH;
    float* out_chat1 = out + (size_t)2 * NB * NH + (size_t)NB * NZ;

    // 1. build concatenated activations
    concat_kernel<<<1024, 256>>>((const float4*)x, (const float4*)h0, (const float4*)hhat0);

    // 2. hyper GEMM: hg = hcat @ hweight + hbias   [2048,1024], K=2304
    sgemm128<<<dim3(8, 16), 256>>>(p_hcat, hweight, p_hg,
                                   2304, 2304, 1024, 1024,
                                   hbias, nullptr, nullptr, nullptr);

    // 3. hyper cell -> hhat1, chat1 (into output buffer)
    hyper_cell<<<(NB * NZ) / 256, 256>>>(chat0, out_hhat1, out_chat1);

    // 4. embedding GEMMs: z_* = hhat1 @ zweight_* (+bias)   [2048,256] each, K=256
    sgemm128<<<dim3(2, 16), 256>>>(out_hhat1, zw_h, p_z + 0,
                                   256, 256, 256, 768, zb_h, nullptr, nullptr, nullptr);
    sgemm128<<<dim3(2, 16), 256>>>(out_hhat1, zw_x, p_z + 256,
                                   256, 256, 256, 768, zb_x, nullptr, nullptr, nullptr);
    sgemm128<<<dim3(2, 16), 256>>>(out_hhat1, zw_b, p_z + 512,
                                   256, 256, 256, 768, nullptr, nullptr, nullptr, nullptr);

    // 5. modulation GEMMs: d_y*[.,g*H:..] = z_*[:,g] @ dweight_*[g]   K=64, 12 GEMMs
    {
        const float* dws[3] = {dw_h, dw_x, dw_b};
        float* dys[3] = {p_dyh, p_dyx, p_dyb};
        for (int w = 0; w < 3; w++)
            for (int g = 0; g < 4; g++)
                sgemm128<<<dim3(8, 16), 256>>>(p_z + w * 256 + g * 64,
                                               dws[w] + (size_t)g * NE * NH,
                                               dys[w] + g * NH,
                                               64, 768, 1024, 4096,
                                               nullptr, nullptr, nullptr, nullptr);
    }

    // 6. main GEMM with fused modulation epilogue:
    //    gates = (cat2 @ weight) * d_yh * d_yx + d_yb + bias   [2048,4096], K=2048
    sgemm128<<<dim3(32, 16), 256>>>(p_cat2, weight, p_gates,
                                    2048, 2048, 4096, 4096,
                                    bias, p_dyh, p_dyx, p_dyb);

    // 7. main cell -> h1, c1
    main_cell<<<(NB * NH) / 256, 256>>>(c0, out_h1, out_c1);
}

// round 3
// speedup vs baseline: 2.0034x; 2.0034x over previous
#include <cuda_runtime.h>
#include <cstdint>
#include <math.h>

// Problem dims
#define NB 2048
#define ND 1024
#define NH 1024
#define NZ 256
#define NE 64

// ---------------- scratch (static device globals; no allocation) ----------------
__device__ __align__(16) float g_hcat[NB * (NZ + NH + ND)];   // [B, 2304]
__device__ __align__(16) float g_cat2[NB * (NH + ND)];        // [B, 2048]
__device__ __align__(16) float g_hg[NB * 4 * NZ];             // [B, 1024]
__device__ __align__(16) float g_z[NB * 3 * 4 * NE];          // [B, 768] = [z_h|z_x|z_b]
__device__ __align__(16) float g_zwcat[256 * 768];            // [256, 768] = [zw_h|zw_x|zw_b]
__device__ __align__(16) float g_zbcat[768];
__device__ __align__(16) float g_dyh[NB * 4 * NH];
__device__ __align__(16) float g_dyx[NB * 4 * NH];
__device__ __align__(16) float g_dyb[NB * 4 * NH];
__device__ __align__(16) float g_gates[NB * 4 * NH];

__device__ __forceinline__ float sigf(float v) { return 1.f / (1.f + __expf(-v)); }

__device__ __forceinline__ uint32_t smem_u32(const void* p) {
    uint32_t a;
    asm("{ .reg .u64 t; cvta.to.shared.u64 t, %1; cvt.u32.u64 %0, t; }" : "=r"(a) : "l"(p));
    return a;
}
__device__ __forceinline__ uint32_t f2tf32(float x) {
    uint32_t r;
    asm("cvt.rna.tf32.f32 %0, %1;" : "=r"(r) : "f"(x));
    return r;
}

#define LDSM_X4(r, addr) \
    asm volatile("ldmatrix.sync.aligned.m8n8.x4.shared.b16 {%0,%1,%2,%3}, [%4];" \
        : "=r"((r)[0]), "=r"((r)[1]), "=r"((r)[2]), "=r"((r)[3]) : "r"(addr))

__device__ __forceinline__ void mma_tf32(float* d, const uint32_t* a, const uint32_t* b) {
    asm volatile("mma.sync.aligned.m16n8k8.row.col.f32.tf32.tf32.f32 "
                 "{%0,%1,%2,%3}, {%4,%5,%6,%7}, {%8,%9}, {%0,%1,%2,%3};"
                 : "+f"(d[0]), "+f"(d[1]), "+f"(d[2]), "+f"(d[3])
                 : "r"(a[0]), "r"(a[1]), "r"(a[2]), "r"(a[3]), "r"(b[0]), "r"(b[1]));
}

// ---------------- prep: concatenations ----------------
__global__ void concat_kernel(const float4* __restrict__ x,
                              const float4* __restrict__ h0,
                              const float4* __restrict__ hhat0,
                              const float4* __restrict__ zw_h,
                              const float4* __restrict__ zw_x,
                              const float4* __restrict__ zw_b,
                              const float* __restrict__ zb_h,
                              const float* __restrict__ zb_x) {
    float4* hc = reinterpret_cast<float4*>(g_hcat);
    float4* c2 = reinterpret_cast<float4*>(g_cat2);
    float4* zw = reinterpret_cast<float4*>(g_zwcat);
    const int HC4 = (NZ + NH + ND) / 4;  // 576
    const int N1 = NB * HC4;
    const int stride = gridDim.x * blockDim.x;
    const int t0 = blockIdx.x * blockDim.x + threadIdx.x;
    for (int i = t0; i < N1; i += stride) {
        int b = i / HC4;
        int c = i - b * HC4;
        float4 v;
        if (c < NZ / 4)                 v = hhat0[b * (NZ / 4) + c];
        else if (c < (NZ + NH) / 4)     v = h0[b * (NH / 4) + (c - NZ / 4)];
        else                            v = x[b * (ND / 4) + (c - (NZ + NH) / 4)];
        hc[i] = v;
    }
    const int N2 = NB * 512;
    for (int i = t0; i < N2; i += stride) {
        int b = i >> 9;
        int c = i & 511;
        c2[i] = (c < 256) ? h0[b * 256 + c] : x[b * 256 + (c - 256)];
    }
    // zw_cat: [256 rows][768], row = [zw_h row | zw_x row | zw_b row]
    const int N3 = 256 * 192;  // 192 float4 per row
    for (int i = t0; i < N3; i += stride) {
        int k = i / 192;
        int c = i - k * 192;
        float4 v;
        if (c < 64)       v = zw_h[k * 64 + c];
        else if (c < 128) v = zw_x[k * 64 + (c - 64)];
        else              v = zw_b[k * 64 + (c - 128)];
        zw[i] = v;
    }
    for (int i = t0; i < 768; i += stride)
        g_zbcat[i] = (i < 256) ? zb_h[i] : (i < 512) ? zb_x[i - 256] : 0.f;
}

// ---------------- tf32 mma.sync GEMM core: 128x128 tile, BK=32 ----------------
// C[m,n] = sum_k A[m,k]*W[k,n]; optional epilogue v = v*mh*mx + mb; v += bias.
// Requires M,N multiples of 128, K multiple of 32, A 16B-aligned rows (lda%4==0).
#define SLD 36  // smem row stride in floats (144B): conflict-free for LDSM + STS.128

__device__ __forceinline__ void gemm_core(
    const float* __restrict__ A, int lda,
    const float* __restrict__ W, int ldb,
    float* __restrict__ C, int ldc, int K,
    const float* __restrict__ bias,
    const float* __restrict__ mh, const float* __restrict__ mx,
    const float* __restrict__ mb,
    int bM, int bN) {
    __shared__ __align__(16) float As[128 * SLD];
    __shared__ __align__(16) float Bs[128 * SLD];

    const int tid = threadIdx.x;
    const int lane = tid & 31;
    const int wid = tid >> 5;
    const int wm = (wid & 1) << 6;   // 0 or 64
    const int wn = (wid >> 1) << 5;  // 0,32,64,96

    float acc[4][4][4];
#pragma unroll
    for (int i = 0; i < 4; i++)
#pragma unroll
        for (int j = 0; j < 4; j++)
#pragma unroll
            for (int q = 0; q < 4; q++) acc[i][j][q] = 0.f;

    float4 ga[4], gb[4];

    const uint32_t a_base = smem_u32(As);
    const uint32_t b_base = smem_u32(Bs);
    uint32_t* Asu = reinterpret_cast<uint32_t*>(As);
    uint32_t* Bsu = reinterpret_cast<uint32_t*>(Bs);

    // per-lane ldmatrix address pieces
    const int jj = lane >> 3;          // matrix index 0..3
    const int l7 = lane & 7;
    // A: matrix j -> row off ((j&1)<<3), k byte off ((j>>1)<<4)
    const uint32_t a_off = (uint32_t)((wm + ((jj & 1) << 3) + l7) * (SLD * 4) + ((jj >> 1) << 4));
    // B: matrix j -> n row off ((j>>1)<<3), k byte off ((j&1)<<4)
    const uint32_t b_off = (uint32_t)((wn + ((jj >> 1) << 3) + l7) * (SLD * 4) + ((jj & 1) << 4));

#define LOADG(k0_) do { \
    _Pragma("unroll") \
    for (int i = 0; i < 4; i++) { \
        int idx = tid + (i << 8); \
        int r = idx >> 3, c4 = (idx & 7) << 2; \
        ga[i] = *reinterpret_cast<const float4*>(A + (size_t)(bM + r) * lda + (k0_) + c4); \
        int kk = idx >> 5, n4 = (idx & 31) << 2; \
        gb[i] = *reinterpret_cast<const float4*>(W + (size_t)((k0_) + kk) * ldb + bN + n4); \
    } } while (0)

#define STORES() do { \
    _Pragma("unroll") \
    for (int i = 0; i < 4; i++) { \
        int idx = tid + (i << 8); \
        int r = idx >> 3, c4 = (idx & 7) << 2; \
        uint4 u = make_uint4(f2tf32(ga[i].x), f2tf32(ga[i].y), f2tf32(ga[i].z), f2tf32(ga[i].w)); \
        *reinterpret_cast<uint4*>(&Asu[r * SLD + c4]) = u; \
        int kk = idx >> 5, n4 = (idx & 31) << 2; \
        Bsu[(n4 + 0) * SLD + kk] = f2tf32(gb[i].x); \
        Bsu[(n4 + 1) * SLD + kk] = f2tf32(gb[i].y); \
        Bsu[(n4 + 2) * SLD + kk] = f2tf32(gb[i].z); \
        Bsu[(n4 + 3) * SLD + kk] = f2tf32(gb[i].w); \
    } } while (0)

    const int nch = K >> 5;
    LOADG(0);
    STORES();
    __syncthreads();

    for (int c = 0; c < nch; c++) {
        if (c + 1 < nch) LOADG((c + 1) << 5);

#pragma unroll
        for (int ks = 0; ks < 4; ks++) {
            const uint32_t kb = (uint32_t)(ks << 5);  // k0*4 bytes
            uint32_t af[4][4], bf[2][4];
#pragma unroll
            for (int mf = 0; mf < 4; mf++)
                LDSM_X4(af[mf], a_base + a_off + (uint32_t)(mf * 16 * SLD * 4) + kb);
#pragma unroll
            for (int p = 0; p < 2; p++)
                LDSM_X4(bf[p], b_base + b_off + (uint32_t)(p * 16 * SLD * 4) + kb);
#pragma unroll
            for (int mf = 0; mf < 4; mf++)
#pragma unroll
                for (int nf = 0; nf < 4; nf++)
                    mma_tf32(acc[mf][nf], af[mf], bf[nf >> 1] + ((nf & 1) << 1));
        }
        __syncthreads();
        if (c + 1 < nch) {
            STORES();
            __syncthreads();
        }
    }

    // ---- epilogue ----
    const int r0 = bM + wm + (lane >> 2);
    const int c0 = bN + wn + ((lane & 3) << 1);
#pragma unroll
    for (int mf = 0; mf < 4; mf++) {
#pragma unroll
        for (int half = 0; half < 2; half++) {
            const int row = r0 + mf * 16 + half * 8;
            float* Crow = C + (size_t)row * ldc;
            const float* mhr = mh ? mh + (size_t)row * ldc : nullptr;
            const float* mxr = mx ? mx + (size_t)row * ldc : nullptr;
            const float* mbr = mb ? mb + (size_t)row * ldc : nullptr;
#pragma unroll
            for (int nf = 0; nf < 4; nf++) {
                const int col = c0 + nf * 8;
                float2 v;
                v.x = acc[mf][nf][half * 2 + 0];
                v.y = acc[mf][nf][half * 2 + 1];
                if (mh) {
                    float2 vh = *reinterpret_cast<const float2*>(mhr + col);
                    float2 vx = *reinterpret_cast<const float2*>(mxr + col);
                    float2 vb = *reinterpret_cast<const float2*>(mbr + col);
                    v.x = v.x * vh.x * vx.x + vb.x;
                    v.y = v.y * vh.y * vx.y + vb.y;
                }
                if (bias) {
                    float2 bb = *reinterpret_cast<const float2*>(bias + col);
                    v.x += bb.x;
                    v.y += bb.y;
                }
                *reinterpret_cast<float2*>(Crow + col) = v;
            }
        }
    }
#undef LOADG
#undef STORES
}

__global__ __launch_bounds__(256)
void tgemm(const float* __restrict__ A, int lda,
           const float* __restrict__ W, int ldb,
           float* __restrict__ C, int ldc, int K,
           const float* __restrict__ bias,
           const float* __restrict__ mh, const float* __restrict__ mx,
           const float* __restrict__ mb) {
    gemm_core(A, lda, W, ldb, C, ldc, K, bias, mh, mx, mb,
              blockIdx.y * 128, blockIdx.x * 128);
}

// 12 modulation GEMMs in one launch: z = blockIdx.z -> (w, g)
__global__ __launch_bounds__(256)
void mod_gemm(const float* __restrict__ dwh, const float* __restrict__ dwx,
              const float* __restrict__ dwb) {
    const int w = blockIdx.z >> 2;
    const int g = blockIdx.z & 3;
    const float* W = (w == 0 ? dwh : w == 1 ? dwx : dwb) + (size_t)g * NE * NH;
    const float* A = g_z + w * 256 + g * 64;
    float* Cp = (w == 0 ? g_dyh : w == 1 ? g_dyx : g_dyb) + g * NH;
    gemm_core(A, 768, W, NH, Cp, 4 * NH, 64, nullptr, nullptr, nullptr, nullptr,
              blockIdx.y * 128, blockIdx.x * 128);
}

// ---------------- elementwise cells ----------------
__global__ void hyper_cell(const float* __restrict__ chat0,
                           float* __restrict__ out_hhat1,
                           float* __restrict__ out_chat1) {
    int idx = blockIdx.x * blockDim.x + threadIdx.x;
    if (idx >= NB * NZ) return;
    int b = idx >> 8;
    int z = idx & (NZ - 1);
    const float* row = g_hg + (size_t)b * (4 * NZ);
    float iv = row[z], gv = row[NZ + z], fv = row[2 * NZ + z], ov = row[3 * NZ + z];
    float c1 = sigf(fv) * chat0[idx] + sigf(iv) * tanhf(gv);
    out_chat1[idx] = c1;
    out_hhat1[idx] = sigf(ov) * tanhf(c1);
}

__global__ void main_cell(const float* __restrict__ c0,
                          float* __restrict__ out_h1,
                          float* __restrict__ out_c1) {
    int idx = blockIdx.x * blockDim.x + threadIdx.x;
    if (idx >= NB * NH) return;
    int b = idx >> 10;
    int h = idx & (NH - 1);
    const float* row = g_gates + (size_t)b * (4 * NH);
    float iv = row[h], gv = row[NH + h], fv = row[2 * NH + h], ov = row[3 * NH + h];
    float c1 = sigf(fv) * c0[idx] + sigf(iv) * tanhf(gv);
    out_c1[idx] = c1;
    out_h1[idx] = sigf(ov) * tanhf(c1);
}

// ---------------- launch ----------------
extern "C" void kernel_launch(void* const* d_in, const int* in_sizes, int n_in,
                              void* d_out, int out_size) {
    const float* x       = (const float*)d_in[0];
    const float* h0      = (const float*)d_in[1];
    const float* c0      = (const float*)d_in[2];
    const float* hhat0   = (const float*)d_in[3];
    const float* chat0   = (const float*)d_in[4];
    const float* hweight = (const float*)d_in[5];
    const float* hbias   = (const float*)d_in[6];
    const float* zw_h    = (const float*)d_in[7];
    const float* zw_x    = (const float*)d_in[8];
    const float* zw_b    = (const float*)d_in[9];
    const float* zb_h    = (const float*)d_in[10];
    const float* zb_x    = (const float*)d_in[11];
    const float* dw_h    = (const float*)d_in[12];
    const float* dw_x    = (const float*)d_in[13];
    const float* dw_b    = (const float*)d_in[14];
    const float* weight  = (const float*)d_in[15];
    const float* bias    = (const float*)d_in[16];
    float* out = (float*)d_out;

    float *p_hcat, *p_cat2, *p_hg, *p_z, *p_zw, *p_zb, *p_dyh, *p_dyx, *p_dyb, *p_gates;
    cudaGetSymbolAddress((void**)&p_hcat, g_hcat);
    cudaGetSymbolAddress((void**)&p_cat2, g_cat2);
    cudaGetSymbolAddress((void**)&p_hg, g_hg);
    cudaGetSymbolAddress((void**)&p_z, g_z);
    cudaGetSymbolAddress((void**)&p_zw, g_zwcat);
    cudaGetSymbolAddress((void**)&p_zb, g_zbcat);
    cudaGetSymbolAddress((void**)&p_dyh, g_dyh);
    cudaGetSymbolAddress((void**)&p_dyx, g_dyx);
    cudaGetSymbolAddress((void**)&p_dyb, g_dyb);
    cudaGetSymbolAddress((void**)&p_gates, g_gates);

    float* out_h1    = out;
    float* out_c1    = out + (size_t)NB * NH;
    float* out_hhat1 = out + (size_t)2 * NB * NH;
    float* out_chat1 = out + (size_t)2 * NB * NH + (size_t)NB * NZ;

    // 1. concat prep
    concat_kernel<<<1024, 256>>>((const float4*)x, (const float4*)h0,
                                 (const float4*)hhat0,
                                 (const float4*)zw_h, (const float4*)zw_x,
                                 (const float4*)zw_b, zb_h, zb_x);

    // 2. hyper GEMM: hg = hcat @ hweight + hbias  [2048,1024], K=2304
    tgemm<<<dim3(8, 16), 256>>>(p_hcat, 2304, hweight, 1024, p_hg, 1024, 2304,
                                hbias, nullptr, nullptr, nullptr);

    // 3. hyper cell
    hyper_cell<<<(NB * NZ) / 256, 256>>>(chat0, out_hhat1, out_chat1);

    // 4. fused z GEMM: z = hhat1 @ zw_cat + zb_cat  [2048,768], K=256
    tgemm<<<dim3(6, 16), 256>>>(out_hhat1, 256, p_zw, 768, p_z, 768, 256,
                                p_zb, nullptr, nullptr, nullptr);

    // 5. 12 modulation GEMMs, one launch  [2048,1024] each, K=64
    mod_gemm<<<dim3(8, 16, 12), 256>>>(dw_h, dw_x, dw_b);

    // 6. main GEMM + fused modulation epilogue  [2048,4096], K=2048
    tgemm<<<dim3(32, 16), 256>>>(p_cat2, 2048, weight, 4096, p_gates, 4096, 2048,
                                 bias, p_dyh, p_dyx, p_dyb);

    // 7. main cell
    main_cell<<<(NB * NH) / 256, 256>>>(c0, out_h1, out_c1);
}

// round 4
// speedup vs baseline: 4.1566x; 2.0748x over previous
#include <cuda_runtime.h>
#include <cstdint>
#include <math.h>

// Problem dims
#define NB 2048
#define ND 1024
#define NH 1024
#define NZ 256
#define NE 64

// ---------------- scratch (static device globals; no allocation) ----------------
__device__ __align__(16) float g_hcat[NB * (NZ + NH + ND)];   // tf32 bits [B,2304]
__device__ __align__(16) float g_cat2[NB * (NH + ND)];        // tf32 bits [B,2048]
__device__ __align__(16) float g_hg[NB * 4 * NZ];             // f32 [B,1024]
__device__ __align__(16) float g_hhat1t[NB * NZ];             // tf32 bits [B,256]
__device__ __align__(16) float g_z[NB * 3 * 4 * NE];          // tf32 bits [B,768]
__device__ __align__(16) float g_zbcat[768];
__device__ __align__(16) float g_hwT[1024 * 2304];            // tf32 [N,K]
__device__ __align__(16) float g_wT[4096 * 2048];             // tf32 [N,K]
__device__ __align__(16) float g_zwT[768 * 256];              // tf32 [N,K]
__device__ __align__(16) float g_dwT[12 * 1024 * 64];         // tf32 [w*4+g][N=1024][K=64]
__device__ __align__(16) float g_dyh[NB * 4 * NH];
__device__ __align__(16) float g_dyx[NB * 4 * NH];
__device__ __align__(16) float g_dyb[NB * 4 * NH];
__device__ __align__(16) float g_gates[NB * 4 * NH];

__device__ __forceinline__ float sigf(float v) { return 1.f / (1.f + __expf(-v)); }

__device__ __forceinline__ uint32_t smem_u32(const void* p) {
    uint32_t a;
    asm("{ .reg .u64 t; cvta.to.shared.u64 t, %1; cvt.u32.u64 %0, t; }" : "=r"(a) : "l"(p));
    return a;
}
__device__ __forceinline__ uint32_t f2tf32(float x) {
    uint32_t r;
    asm("cvt.rna.tf32.f32 %0, %1;" : "=r"(r) : "f"(x));
    return r;
}
__device__ __forceinline__ float f2tf32f(float x) { return __uint_as_float(f2tf32(x)); }

__device__ __forceinline__ void cpasync16(uint32_t saddr, const void* gaddr) {
    asm volatile("cp.async.cg.shared.global [%0], [%1], 16;" :: "r"(saddr), "l"(gaddr));
}

#define LDSM_X4(r, addr) \
    asm volatile("ldmatrix.sync.aligned.m8n8.x4.shared.b16 {%0,%1,%2,%3}, [%4];" \
        : "=r"((r)[0]), "=r"((r)[1]), "=r"((r)[2]), "=r"((r)[3]) : "r"(addr))

__device__ __forceinline__ void mma_tf32(float* d, const uint32_t* a, const uint32_t* b) {
    asm volatile("mma.sync.aligned.m16n8k8.row.col.f32.tf32.tf32.f32 "
                 "{%0,%1,%2,%3}, {%4,%5,%6,%7}, {%8,%9}, {%0,%1,%2,%3};"
                 : "+f"(d[0]), "+f"(d[1]), "+f"(d[2]), "+f"(d[3])
                 : "r"(a[0]), "r"(a[1]), "r"(a[2]), "r"(a[3]), "r"(b[0]), "r"(b[1]));
}

// ---------------- prep 1: concat + tf32 convert activations ----------------
__global__ void concat_kernel(const float4* __restrict__ x,
                              const float4* __restrict__ h0,
                              const float4* __restrict__ hhat0,
                              const float* __restrict__ zb_h,
                              const float* __restrict__ zb_x) {
    float4* hc = reinterpret_cast<float4*>(g_hcat);
    float4* c2 = reinterpret_cast<float4*>(g_cat2);
    const int HC4 = (NZ + NH + ND) / 4;  // 576
    const int N1 = NB * HC4;
    const int stride = gridDim.x * blockDim.x;
    const int t0 = blockIdx.x * blockDim.x + threadIdx.x;
    for (int i = t0; i < N1; i += stride) {
        int b = i / HC4;
        int c = i - b * HC4;
        float4 v;
        if (c < NZ / 4)                 v = hhat0[b * (NZ / 4) + c];
        else if (c < (NZ + NH) / 4)     v = h0[b * (NH / 4) + (c - NZ / 4)];
        else                            v = x[b * (ND / 4) + (c - (NZ + NH) / 4)];
        v.x = f2tf32f(v.x); v.y = f2tf32f(v.y); v.z = f2tf32f(v.z); v.w = f2tf32f(v.w);
        hc[i] = v;
    }
    const int N2 = NB * 512;
    for (int i = t0; i < N2; i += stride) {
        int b = i >> 9;
        int c = i & 511;
        float4 v = (c < 256) ? h0[b * 256 + c] : x[b * 256 + (c - 256)];
        v.x = f2tf32f(v.x); v.y = f2tf32f(v.y); v.z = f2tf32f(v.z); v.w = f2tf32f(v.w);
        c2[i] = v;
    }
    for (int i = t0; i < 768; i += stride)
        g_zbcat[i] = (i < 256) ? zb_h[i] : (i < 512) ? zb_x[i - 256] : 0.f;
}

// ---------------- prep 2: transpose + tf32 convert all weights ----------------
// One 1-D grid covering 17 matrices via cumulative tile offsets.
// tiles: hweight 2304 | weight 8192 | zw_h/x/b 64 each | dw 64 each x12 = 11456
__global__ __launch_bounds__(256)
void transpose_all(const float* __restrict__ hw, const float* __restrict__ w,
                   const float* __restrict__ zh, const float* __restrict__ zx,
                   const float* __restrict__ zb,
                   const float* __restrict__ dh, const float* __restrict__ dx,
                   const float* __restrict__ db) {
    __shared__ float t[32][33];
    int b = blockIdx.x;
    const float* in; float* out; int K, N, lt;
    if (b < 2304)       { in = hw; out = g_hwT; K = 2304; N = 1024; lt = b; }
    else if (b < 10496) { in = w;  out = g_wT;  K = 2048; N = 4096; lt = b - 2304; }
    else if (b < 10688) {
        int i = (b - 10496) >> 6;  // 0..2
        in = (i == 0 ? zh : i == 1 ? zx : zb);
        out = g_zwT + i * 256 * 256;
        K = 256; N = 256; lt = (b - 10496) & 63;
    } else {
        int i = (b - 10688) >> 6;  // 0..11
        int wsel = i / 4, g = i & 3;
        in = (wsel == 0 ? dh : wsel == 1 ? dx : db) + (size_t)g * 64 * 1024;
        out = g_dwT + (size_t)i * 1024 * 64;
        K = 64; N = 1024; lt = (b - 10688) & 63;
    }
    const int ntx = N >> 5;
    const int tx = lt % ntx, ty = lt / ntx;
    const int lx = threadIdx.x & 31, ly = threadIdx.x >> 5;
#pragma unroll
    for (int j = 0; j < 4; j++) {
        int k = ly + j * 8;
        t[k][lx] = in[(size_t)(ty * 32 + k) * N + tx * 32 + lx];
    }
    __syncthreads();
#pragma unroll
    for (int j = 0; j < 4; j++) {
        int r = ly + j * 8;  // n within tile
        out[(size_t)(tx * 32 + r) * K + ty * 32 + lx] = f2tf32f(t[lx][r]);
    }
}

// ---------------- tf32 GEMM core: 128x128 tile, BK=32, cp.async 2-stage ----------------
#define SLD 36
#define TILE_B (128 * SLD * 4)      // 18432 bytes per operand tile
#define STAGE_B (2 * TILE_B)        // 36864 per stage
#define SMEM_TOT (2 * STAGE_B)      // 73728

__device__ __forceinline__ void gemm_core(
    const float* __restrict__ A, int lda,
    const float* __restrict__ Wt,         // [N,K] rows, stride K
    float* __restrict__ C, int ldc, int K,
    const float* __restrict__ bias,
    const float* __restrict__ mh, const float* __restrict__ mx,
    const float* __restrict__ mb, int cvt,
    int bM, int bN) {
    extern __shared__ __align__(16) char dynsmem[];
    const uint32_t sbase = smem_u32(dynsmem);

    const int tid = threadIdx.x;
    const int lane = tid & 31;
    const int wid = tid >> 5;
    const int wm = (wid & 1) << 6;
    const int wn = (wid >> 1) << 5;

    float acc[4][4][4];
#pragma unroll
    for (int i = 0; i < 4; i++)
#pragma unroll
        for (int j = 0; j < 4; j++)
#pragma unroll
            for (int q = 0; q < 4; q++) acc[i][j][q] = 0.f;

    const int jj = lane >> 3;
    const int l7 = lane & 7;
    const uint32_t a_off = (uint32_t)((wm + ((jj & 1) << 3) + l7) * (SLD * 4) + ((jj >> 1) << 4));
    const uint32_t b_off = (uint32_t)((wn + ((jj >> 1) << 3) + l7) * (SLD * 4) + ((jj & 1) << 4));

    const int r_ld = tid >> 3;           // 0..31 step rows (4 iters of +32)... actually idx>>3
    const int c4 = (tid & 7) << 2;

    const float* Arow = A + (size_t)bM * lda;
    const float* Brow = Wt + (size_t)bN * K;

#define ISSUE(c_, st_) do { \
    uint32_t sa = sbase + (st_) * STAGE_B; \
    uint32_t sb = sa + TILE_B; \
    int k0 = (c_) << 5; \
    _Pragma("unroll") \
    for (int i = 0; i < 4; i++) { \
        int r = r_ld + (i << 5); \
        uint32_t so = (uint32_t)((r * SLD + c4) << 2); \
        cpasync16(sa + so, Arow + (size_t)r * lda + k0 + c4); \
        cpasync16(sb + so, Brow + (size_t)r * K + k0 + c4); \
    } \
    asm volatile("cp.async.commit_group;" ::: "memory"); \
} while (0)

    const int nch = K >> 5;
    ISSUE(0, 0);
    for (int c = 0; c < nch; c++) {
        if (c + 1 < nch) {
            ISSUE(c + 1, (c + 1) & 1);
            asm volatile("cp.async.wait_group 1;" ::: "memory");
        } else {
            asm volatile("cp.async.wait_group 0;" ::: "memory");
        }
        __syncthreads();

        const uint32_t a_base = sbase + (c & 1) * STAGE_B;
        const uint32_t b_base = a_base + TILE_B;
#pragma unroll
        for (int ks = 0; ks < 4; ks++) {
            const uint32_t kb = (uint32_t)(ks << 5);
            uint32_t af[4][4], bf[2][4];
#pragma unroll
            for (int mf = 0; mf < 4; mf++)
                LDSM_X4(af[mf], a_base + a_off + (uint32_t)(mf * 16 * SLD * 4) + kb);
#pragma unroll
            for (int p = 0; p < 2; p++)
                LDSM_X4(bf[p], b_base + b_off + (uint32_t)(p * 16 * SLD * 4) + kb);
#pragma unroll
            for (int mf = 0; mf < 4; mf++)
#pragma unroll
                for (int nf = 0; nf < 4; nf++)
                    mma_tf32(acc[mf][nf], af[mf], bf[nf >> 1] + ((nf & 1) << 1));
        }
        __syncthreads();
    }
#undef ISSUE

    // ---- epilogue ----
    const int r0 = bM + wm + (lane >> 2);
    const int c0 = bN + wn + ((lane & 3) << 1);
#pragma unroll
    for (int mf = 0; mf < 4; mf++) {
#pragma unroll
        for (int half = 0; half < 2; half++) {
            const int row = r0 + mf * 16 + half * 8;
            float* Crow = C + (size_t)row * ldc;
            const float* mhr = mh ? mh + (size_t)row * ldc : nullptr;
            const float* mxr = mx ? mx + (size_t)row * ldc : nullptr;
            const float* mbr = mb ? mb + (size_t)row * ldc : nullptr;
#pragma unroll
            for (int nf = 0; nf < 4; nf++) {
                const int col = c0 + nf * 8;
                float2 v;
                v.x = acc[mf][nf][half * 2 + 0];
                v.y = acc[mf][nf][half * 2 + 1];
                if (mh) {
                    float2 vh = *reinterpret_cast<const float2*>(mhr + col);
                    float2 vx = *reinterpret_cast<const float2*>(mxr + col);
                    float2 vb = *reinterpret_cast<const float2*>(mbr + col);
                    v.x = v.x * vh.x * vx.x + vb.x;
                    v.y = v.y * vh.y * vx.y + vb.y;
                }
                if (bias) {
                    float2 bb = *reinterpret_cast<const float2*>(bias + col);
                    v.x += bb.x;
                    v.y += bb.y;
                }
                if (cvt) { v.x = f2tf32f(v.x); v.y = f2tf32f(v.y); }
                *reinterpret_cast<float2*>(Crow + col) = v;
            }
        }
    }
}

__global__ __launch_bounds__(256, 2)
void tgemm(const float* __restrict__ A, int lda,
           const float* __restrict__ Wt,
           float* __restrict__ C, int ldc, int K,
           const float* __restrict__ bias,
           const float* __restrict__ mh, const float* __restrict__ mx,
           const float* __restrict__ mb, int cvt) {
    gemm_core(A, lda, Wt, C, ldc, K, bias, mh, mx, mb, cvt,
              blockIdx.y * 128, blockIdx.x * 128);
}

// 12 modulation GEMMs in one launch: blockIdx.z -> (w, g)
__global__ __launch_bounds__(256, 2)
void mod_gemm() {
    const int w = blockIdx.z >> 2;
    const int g = blockIdx.z & 3;
    const float* A = g_z + w * 256 + g * 64;
    const float* Wt = g_dwT + (size_t)blockIdx.z * 1024 * 64;
    float* Cp = (w == 0 ? g_dyh : w == 1 ? g_dyx : g_dyb) + g * NH;
    gemm_core(A, 768, Wt, Cp, 4 * NH, 64, nullptr, nullptr, nullptr, nullptr, 0,
              blockIdx.y * 128, blockIdx.x * 128);
}

// ---------------- elementwise cells ----------------
__global__ void hyper_cell(const float* __restrict__ chat0,
                           float* __restrict__ out_hhat1,
                           float* __restrict__ out_chat1) {
    int idx = blockIdx.x * blockDim.x + threadIdx.x;
    if (idx >= NB * NZ) return;
    int b = idx >> 8;
    int z = idx & (NZ - 1);
    const float* row = g_hg + (size_t)b * (4 * NZ);
    float iv = row[z], gv = row[NZ + z], fv = row[2 * NZ + z], ov = row[3 * NZ + z];
    float c1 = sigf(fv) * chat0[idx] + sigf(iv) * tanhf(gv);
    float h1 = sigf(ov) * tanhf(c1);
    out_chat1[idx] = c1;
    out_hhat1[idx] = h1;
    g_hhat1t[idx] = f2tf32f(h1);
}

__global__ void main_cell(const float* __restrict__ c0,
                          float* __restrict__ out_h1,
                          float* __restrict__ out_c1) {
    int idx = blockIdx.x * blockDim.x + threadIdx.x;
    if (idx >= NB * NH) return;
    int b = idx >> 10;
    int h = idx & (NH - 1);
    const float* row = g_gates + (size_t)b * (4 * NH);
    float iv = row[h], gv = row[NH + h], fv = row[2 * NH + h], ov = row[3 * NH + h];
    float c1 = sigf(fv) * c0[idx] + sigf(iv) * tanhf(gv);
    out_c1[idx] = c1;
    out_h1[idx] = sigf(ov) * tanhf(c1);
}

// ---------------- launch ----------------
extern "C" void kernel_launch(void* const* d_in, const int* in_sizes, int n_in,
                              void* d_out, int out_size) {
    const float* x       = (const float*)d_in[0];
    const float* h0      = (const float*)d_in[1];
    const float* c0      = (const float*)d_in[2];
    const float* hhat0   = (const float*)d_in[3];
    const float* chat0   = (const float*)d_in[4];
    const float* hweight = (const float*)d_in[5];
    const float* hbias   = (const float*)d_in[6];
    const float* zw_h    = (const float*)d_in[7];
    const float* zw_x    = (const float*)d_in[8];
    const float* zw_b    = (const float*)d_in[9];
    const float* zb_h    = (const float*)d_in[10];
    const float* zb_x    = (const float*)d_in[11];
    const float* dw_h    = (const float*)d_in[12];
    const float* dw_x    = (const float*)d_in[13];
    const float* dw_b    = (const float*)d_in[14];
    const float* weight  = (const float*)d_in[15];
    const float* bias    = (const float*)d_in[16];
    float* out = (float*)d_out;

    static int smem_set = 0;
    if (!smem_set) {
        cudaFuncSetAttribute(tgemm, cudaFuncAttributeMaxDynamicSharedMemorySize, SMEM_TOT);
        cudaFuncSetAttribute(mod_gemm, cudaFuncAttributeMaxDynamicSharedMemorySize, SMEM_TOT);
        smem_set = 1;
    }

    float *p_hcat, *p_cat2, *p_hg, *p_hhat1t, *p_z, *p_zb, *p_hwT, *p_wT, *p_zwT;
    float *p_dyh, *p_dyx, *p_dyb, *p_gates;
    cudaGetSymbolAddress((void**)&p_hcat, g_hcat);
    cudaGetSymbolAddress((void**)&p_cat2, g_cat2);
    cudaGetSymbolAddress((void**)&p_hg, g_hg);
    cudaGetSymbolAddress((void**)&p_hhat1t, g_hhat1t);
    cudaGetSymbolAddress((void**)&p_z, g_z);
    cudaGetSymbolAddress((void**)&p_zb, g_zbcat);
    cudaGetSymbolAddress((void**)&p_hwT, g_hwT);
    cudaGetSymbolAddress((void**)&p_wT, g_wT);
    cudaGetSymbolAddress((void**)&p_zwT, g_zwT);
    cudaGetSymbolAddress((void**)&p_dyh, g_dyh);
    cudaGetSymbolAddress((void**)&p_dyx, g_dyx);
    cudaGetSymbolAddress((void**)&p_dyb, g_dyb);
    cudaGetSymbolAddress((void**)&p_gates, g_gates);

    float* out_h1    = out;
    float* out_c1    = out + (size_t)NB * NH;
    float* out_hhat1 = out + (size_t)2 * NB * NH;
    float* out_chat1 = out + (size_t)2 * NB * NH + (size_t)NB * NZ;

    // 1. prep: concat + convert activations; transpose + convert weights
    concat_kernel<<<1024, 256>>>((const float4*)x, (const float4*)h0,
                                 (const float4*)hhat0, zb_h, zb_x);
    transpose_all<<<11456, 256>>>(hweight, weight, zw_h, zw_x, zw_b, dw_h, dw_x, dw_b);

    // 2. hyper GEMM: hg = hcat @ hweight + hbias  [2048,1024], K=2304
    tgemm<<<dim3(8, 16), 256, SMEM_TOT>>>(p_hcat, 2304, p_hwT, p_hg, 1024, 2304,
                                          hbias, nullptr, nullptr, nullptr, 0);

    // 3. hyper cell
    hyper_cell<<<(NB * NZ) / 256, 256>>>(chat0, out_hhat1, out_chat1);

    // 4. fused z GEMM: z = hhat1 @ zw_cat + zb_cat  [2048,768], K=256 (tf32 output)
    tgemm<<<dim3(6, 16), 256, SMEM_TOT>>>(p_hhat1t, 256, p_zwT, p_z, 768, 256,
                                          p_zb, nullptr, nullptr, nullptr, 1);

    // 5. 12 modulation GEMMs, one launch  [2048,1024] each, K=64
    mod_gemm<<<dim3(8, 16, 12), 256, SMEM_TOT>>>();

    // 6. main GEMM + fused modulation epilogue  [2048,4096], K=2048
    tgemm<<<dim3(32, 16), 256, SMEM_TOT>>>(p_cat2, 2048, p_wT, p_gates, 4096, 2048,
                                           bias, p_dyh, p_dyx, p_dyb, 0);

    // 7. main cell
    main_cell<<<(NB * NH) / 256, 256>>>(c0, out_h1, out_c1);
}

// round 5
// speedup vs baseline: 6.6640x; 1.6032x over previous
#include <cuda_runtime.h>
#include <cuda_fp16.h>
#include <cstdint>
#include <math.h>

// Problem dims
#define NB 2048
#define ND 1024
#define NH 1024
#define NZ 256
#define NE 64

// ---------------- scratch (static device globals; no allocation) ----------------
__device__ __align__(16) __half g_hcat[NB * (NZ + NH + ND)];  // [B,2304]
__device__ __align__(16) __half g_cat2[NB * (NH + ND)];       // [B,2048]
__device__ __align__(16) float  g_hg[NB * 4 * NZ];            // [B,1024]
__device__ __align__(16) __half g_hhat1h[NB * NZ];            // [B,256]
__device__ __align__(16) __half g_z[NB * 3 * 4 * NE];         // [B,768]
__device__ __align__(16) float  g_zbcat[768];
__device__ __align__(16) __half g_hwT[1024 * 2304];           // [N,K]
__device__ __align__(16) __half g_wT[4096 * 2048];            // [N,K]
__device__ __align__(16) __half g_zwT[768 * 256];             // [N,K]
__device__ __align__(16) __half g_dwT[12 * 1024 * 64];        // [w*4+g][N=1024][K=64]
__device__ __align__(16) __half g_dyh[NB * 4 * NH];
__device__ __align__(16) __half g_dyx[NB * 4 * NH];
__device__ __align__(16) __half g_dyb[NB * 4 * NH];
__device__ __align__(16) float  g_gates[NB * 4 * NH];

__device__ __forceinline__ float sigf(float v) { return 1.f / (1.f + __expf(-v)); }

__device__ __forceinline__ uint32_t smem_u32(const void* p) {
    uint32_t a;
    asm("{ .reg .u64 t; cvta.to.shared.u64 t, %1; cvt.u32.u64 %0, t; }" : "=r"(a) : "l"(p));
    return a;
}
__device__ __forceinline__ void cpasync16(uint32_t saddr, const void* gaddr) {
    asm volatile("cp.async.cg.shared.global [%0], [%1], 16;" :: "r"(saddr), "l"(gaddr));
}

#define LDSM_X4(r, addr) \
    asm volatile("ldmatrix.sync.aligned.m8n8.x4.shared.b16 {%0,%1,%2,%3}, [%4];" \
        : "=r"((r)[0]), "=r"((r)[1]), "=r"((r)[2]), "=r"((r)[3]) : "r"(addr))

__device__ __forceinline__ void mma_f16(float* d, const uint32_t* a, const uint32_t* b) {
    asm volatile("mma.sync.aligned.m16n8k16.row.col.f32.f16.f16.f32 "
                 "{%0,%1,%2,%3}, {%4,%5,%6,%7}, {%8,%9}, {%0,%1,%2,%3};"
                 : "+f"(d[0]), "+f"(d[1]), "+f"(d[2]), "+f"(d[3])
                 : "r"(a[0]), "r"(a[1]), "r"(a[2]), "r"(a[3]), "r"(b[0]), "r"(b[1]));
}

__device__ __forceinline__ uint2 f4_to_h4(float4 v) {
    __half2 a = __floats2half2_rn(v.x, v.y);
    __half2 b = __floats2half2_rn(v.z, v.w);
    uint2 r;
    r.x = *reinterpret_cast<uint32_t*>(&a);
    r.y = *reinterpret_cast<uint32_t*>(&b);
    return r;
}

// ---------------- prep 1: concat + fp16 convert activations ----------------
__global__ void concat_kernel(const float4* __restrict__ x,
                              const float4* __restrict__ h0,
                              const float4* __restrict__ hhat0,
                              const float* __restrict__ zb_h,
                              const float* __restrict__ zb_x) {
    uint2* hc = reinterpret_cast<uint2*>(g_hcat);
    uint2* c2 = reinterpret_cast<uint2*>(g_cat2);
    const int HC4 = (NZ + NH + ND) / 4;  // 576
    const int N1 = NB * HC4;
    const int stride = gridDim.x * blockDim.x;
    const int t0 = blockIdx.x * blockDim.x + threadIdx.x;
    for (int i = t0; i < N1; i += stride) {
        int b = i / HC4;
        int c = i - b * HC4;
        float4 v;
        if (c < NZ / 4)                 v = hhat0[b * (NZ / 4) + c];
        else if (c < (NZ + NH) / 4)     v = h0[b * (NH / 4) + (c - NZ / 4)];
        else                            v = x[b * (ND / 4) + (c - (NZ + NH) / 4)];
        hc[i] = f4_to_h4(v);
    }
    const int N2 = NB * 512;
    for (int i = t0; i < N2; i += stride) {
        int b = i >> 9;
        int c = i & 511;
        float4 v = (c < 256) ? h0[b * 256 + c] : x[b * 256 + (c - 256)];
        c2[i] = f4_to_h4(v);
    }
    for (int i = t0; i < 768; i += stride)
        g_zbcat[i] = (i < 256) ? zb_h[i] : (i < 512) ? zb_x[i - 256] : 0.f;
}

// ---------------- prep 2: transpose + fp16 convert all weights ----------------
__global__ __launch_bounds__(256)
void transpose_all(const float* __restrict__ hw, const float* __restrict__ w,
                   const float* __restrict__ zh, const float* __restrict__ zx,
                   const float* __restrict__ zb,
                   const float* __restrict__ dh, const float* __restrict__ dx,
                   const float* __restrict__ db) {
    __shared__ float t[32][33];
    int b = blockIdx.x;
    const float* in; __half* out; int K, N, lt;
    if (b < 2304)       { in = hw; out = g_hwT; K = 2304; N = 1024; lt = b; }
    else if (b < 10496) { in = w;  out = g_wT;  K = 2048; N = 4096; lt = b - 2304; }
    else if (b < 10688) {
        int i = (b - 10496) >> 6;  // 0..2
        in = (i == 0 ? zh : i == 1 ? zx : zb);
        out = g_zwT + i * 256 * 256;
        K = 256; N = 256; lt = (b - 10496) & 63;
    } else {
        int i = (b - 10688) >> 6;  // 0..11
        int wsel = i / 4, g = i & 3;
        in = (wsel == 0 ? dh : wsel == 1 ? dx : db) + (size_t)g * 64 * 1024;
        out = g_dwT + (size_t)i * 1024 * 64;
        K = 64; N = 1024; lt = (b - 10688) & 63;
    }
    const int ntx = N >> 5;
    const int tx = lt % ntx, ty = lt / ntx;
    const int lx = threadIdx.x & 31, ly = threadIdx.x >> 5;
#pragma unroll
    for (int j = 0; j < 4; j++) {
        int k = ly + j * 8;
        t[k][lx] = in[(size_t)(ty * 32 + k) * N + tx * 32 + lx];
    }
    __syncthreads();
#pragma unroll
    for (int j = 0; j < 4; j++) {
        int r = ly + j * 8;  // n within tile
        out[(size_t)(tx * 32 + r) * K + ty * 32 + lx] = __float2half_rn(t[lx][r]);
    }
}

// ---------------- fp16 GEMM core: 128x128 tile, BK=64 halfs, cp.async 2-stage ----------------
#define SLDH 72                       // smem row stride in halfs (144B), LDSM conflict-free
#define TILE_B (128 * SLDH * 2)       // 18432 bytes per operand tile
#define STAGE_B (2 * TILE_B)          // 36864 per stage
#define SMEM_TOT (2 * STAGE_B)        // 73728

__device__ __forceinline__ void gemm_core(
    const __half* __restrict__ A, int lda,
    const __half* __restrict__ Wt,        // [N,K] rows, stride K
    void* __restrict__ Cv, int ldc, int K,
    const float* __restrict__ bias,
    const __half* __restrict__ mh, const __half* __restrict__ mx,
    const __half* __restrict__ mb, int out_half,
    int bM, int bN) {
    extern __shared__ __align__(16) char dynsmem[];
    const uint32_t sbase = smem_u32(dynsmem);

    const int tid = threadIdx.x;
    const int lane = tid & 31;
    const int wid = tid >> 5;
    const int wm = (wid & 1) << 6;
    const int wn = (wid >> 1) << 5;

    float acc[4][4][4];
#pragma unroll
    for (int i = 0; i < 4; i++)
#pragma unroll
        for (int j = 0; j < 4; j++)
#pragma unroll
            for (int q = 0; q < 4; q++) acc[i][j][q] = 0.f;

    const int jj = lane >> 3;
    const int l7 = lane & 7;
    // A: (jj&1) -> +8 m rows, (jj>>1) -> +16B k  | B: (jj>>1) -> +8 n rows, (jj&1) -> +16B k
    const uint32_t a_off = (uint32_t)((wm + ((jj & 1) << 3) + l7) * (SLDH * 2) + ((jj >> 1) << 4));
    const uint32_t b_off = (uint32_t)((wn + ((jj >> 1) << 3) + l7) * (SLDH * 2) + ((jj & 1) << 4));

    const int r_ld = tid >> 3;           // 0..31 (+32 per iter)
    const int c8 = tid & 7;              // 16B chunk within 128B row

    const __half* Arow = A + (size_t)bM * lda;
    const __half* Brow = Wt + (size_t)bN * K;

#define ISSUE(c_, st_) do { \
    uint32_t sa = sbase + (st_) * STAGE_B; \
    uint32_t sb = sa + TILE_B; \
    int k0 = (c_) << 6; \
    _Pragma("unroll") \
    for (int i = 0; i < 4; i++) { \
        int r = r_ld + (i << 5); \
        uint32_t so = (uint32_t)(r * (SLDH * 2) + (c8 << 4)); \
        cpasync16(sa + so, Arow + (size_t)r * lda + k0 + (c8 << 3)); \
        cpasync16(sb + so, Brow + (size_t)r * K + k0 + (c8 << 3)); \
    } \
    asm volatile("cp.async.commit_group;" ::: "memory"); \
} while (0)

    const int nch = K >> 6;
    ISSUE(0, 0);
    for (int c = 0; c < nch; c++) {
        if (c + 1 < nch) {
            ISSUE(c + 1, (c + 1) & 1);
            asm volatile("cp.async.wait_group 1;" ::: "memory");
        } else {
            asm volatile("cp.async.wait_group 0;" ::: "memory");
        }
        __syncthreads();

        const uint32_t a_base = sbase + (c & 1) * STAGE_B;
        const uint32_t b_base = a_base + TILE_B;
#pragma unroll
        for (int ks = 0; ks < 4; ks++) {
            const uint32_t kb = (uint32_t)(ks << 5);  // 16 halfs = 32B per k-step
            uint32_t af[4][4], bf[2][4];
#pragma unroll
            for (int mf = 0; mf < 4; mf++)
                LDSM_X4(af[mf], a_base + a_off + (uint32_t)(mf * 16 * SLDH * 2) + kb);
#pragma unroll
            for (int p = 0; p < 2; p++)
                LDSM_X4(bf[p], b_base + b_off + (uint32_t)(p * 16 * SLDH * 2) + kb);
#pragma unroll
            for (int mf = 0; mf < 4; mf++)
#pragma unroll
                for (int nf = 0; nf < 4; nf++)
                    mma_f16(acc[mf][nf], af[mf], bf[nf >> 1] + ((nf & 1) << 1));
        }
        __syncthreads();
    }
#undef ISSUE

    // ---- epilogue ----
    const int r0 = bM + wm + (lane >> 2);
    const int c0 = bN + wn + ((lane & 3) << 1);
#pragma unroll
    for (int mf = 0; mf < 4; mf++) {
#pragma unroll
        for (int half = 0; half < 2; half++) {
            const int row = r0 + mf * 16 + half * 8;
            const __half* mhr = mh ? mh + (size_t)row * ldc : nullptr;
            const __half* mxr = mx ? mx + (size_t)row * ldc : nullptr;
            const __half* mbr = mb ? mb + (size_t)row * ldc : nullptr;
#pragma unroll
            for (int nf = 0; nf < 4; nf++) {
                const int col = c0 + nf * 8;
                float2 v;
                v.x = acc[mf][nf][half * 2 + 0];
                v.y = acc[mf][nf][half * 2 + 1];
                if (mh) {
                    float2 vh = __half22float2(*reinterpret_cast<const __half2*>(mhr + col));
                    float2 vx = __half22float2(*reinterpret_cast<const __half2*>(mxr + col));
                    float2 vb = __half22float2(*reinterpret_cast<const __half2*>(mbr + col));
                    v.x = v.x * vh.x * vx.x + vb.x;
                    v.y = v.y * vh.y * vx.y + vb.y;
                }
                if (bias) {
                    float2 bb = *reinterpret_cast<const float2*>(bias + col);
                    v.x += bb.x;
                    v.y += bb.y;
                }
                if (out_half) {
                    __half* Ch = reinterpret_cast<__half*>(Cv) + (size_t)row * ldc + col;
                    *reinterpret_cast<__half2*>(Ch) = __floats2half2_rn(v.x, v.y);
                } else {
                    float* Cf = reinterpret_cast<float*>(Cv) + (size_t)row * ldc + col;
                    *reinterpret_cast<float2*>(Cf) = v;
                }
            }
        }
    }
}

__global__ __launch_bounds__(256, 2)
void tgemm(const __half* __restrict__ A, int lda,
           const __half* __restrict__ Wt,
           void* __restrict__ C, int ldc, int K,
           const float* __restrict__ bias,
           const __half* __restrict__ mh, const __half* __restrict__ mx,
           const __half* __restrict__ mb, int out_half) {
    gemm_core(A, lda, Wt, C, ldc, K, bias, mh, mx, mb, out_half,
              blockIdx.y * 128, blockIdx.x * 128);
}

// 12 modulation GEMMs in one launch: blockIdx.z -> (w, g)
__global__ __launch_bounds__(256, 2)
void mod_gemm() {
    const int w = blockIdx.z >> 2;
    const int g = blockIdx.z & 3;
    const __half* A = g_z + w * 256 + g * 64;
    const __half* Wt = g_dwT + (size_t)blockIdx.z * 1024 * 64;
    __half* Cp = (w == 0 ? g_dyh : w == 1 ? g_dyx : g_dyb) + g * NH;
    gemm_core(A, 768, Wt, Cp, 4 * NH, 64, nullptr, nullptr, nullptr, nullptr, 1,
              blockIdx.y * 128, blockIdx.x * 128);
}

// ---------------- elementwise cells ----------------
__global__ void hyper_cell(const float* __restrict__ chat0,
                           float* __restrict__ out_hhat1,
                           float* __restrict__ out_chat1) {
    int idx = blockIdx.x * blockDim.x + threadIdx.x;
    if (idx >= NB * NZ) return;
    int b = idx >> 8;
    int z = idx & (NZ - 1);
    const float* row = g_hg + (size_t)b * (4 * NZ);
    float iv = row[z], gv = row[NZ + z], fv = row[2 * NZ + z], ov = row[3 * NZ + z];
    float c1 = sigf(fv) * chat0[idx] + sigf(iv) * tanhf(gv);
    float h1 = sigf(ov) * tanhf(c1);
    out_chat1[idx] = c1;
    out_hhat1[idx] = h1;
    g_hhat1h[idx] = __float2half_rn(h1);
}

__global__ void main_cell(const float* __restrict__ c0,
                          float* __restrict__ out_h1,
                          float* __restrict__ out_c1) {
    int idx = blockIdx.x * blockDim.x + threadIdx.x;
    if (idx >= NB * NH) return;
    int b = idx >> 10;
    int h = idx & (NH - 1);
    const float* row = g_gates + (size_t)b * (4 * NH);
    float iv = row[h], gv = row[NH + h], fv = row[2 * NH + h], ov = row[3 * NH + h];
    float c1 = sigf(fv) * c0[idx] + sigf(iv) * tanhf(gv);
    out_c1[idx] = c1;
    out_h1[idx] = sigf(ov) * tanhf(c1);
}

// ---------------- launch ----------------
extern "C" void kernel_launch(void* const* d_in, const int* in_sizes, int n_in,
                              void* d_out, int out_size) {
    const float* x       = (const float*)d_in[0];
    const float* h0      = (const float*)d_in[1];
    const float* c0      = (const float*)d_in[2];
    const float* hhat0   = (const float*)d_in[3];
    const float* chat0   = (const float*)d_in[4];
    const float* hweight = (const float*)d_in[5];
    const float* hbias   = (const float*)d_in[6];
    const float* zw_h    = (const float*)d_in[7];
    const float* zw_x    = (const float*)d_in[8];
    const float* zw_b    = (const float*)d_in[9];
    const float* zb_h    = (const float*)d_in[10];
    const float* zb_x    = (const float*)d_in[11];
    const float* dw_h    = (const float*)d_in[12];
    const float* dw_x    = (const float*)d_in[13];
    const float* dw_b    = (const float*)d_in[14];
    const float* weight  = (const float*)d_in[15];
    const float* bias    = (const float*)d_in[16];
    float* out = (float*)d_out;

    static int smem_set = 0;
    if (!smem_set) {
        cudaFuncSetAttribute(tgemm, cudaFuncAttributeMaxDynamicSharedMemorySize, SMEM_TOT);
        cudaFuncSetAttribute(mod_gemm, cudaFuncAttributeMaxDynamicSharedMemorySize, SMEM_TOT);
        smem_set = 1;
    }

    __half *p_hcat, *p_cat2, *p_hhat1h, *p_z, *p_hwT, *p_wT, *p_zwT;
    __half *p_dyh, *p_dyx, *p_dyb;
    float *p_hg, *p_zb, *p_gates;
    cudaGetSymbolAddress((void**)&p_hcat, g_hcat);
    cudaGetSymbolAddress((void**)&p_cat2, g_cat2);
    cudaGetSymbolAddress((void**)&p_hg, g_hg);
    cudaGetSymbolAddress((void**)&p_hhat1h, g_hhat1h);
    cudaGetSymbolAddress((void**)&p_z, g_z);
    cudaGetSymbolAddress((void**)&p_zb, g_zbcat);
    cudaGetSymbolAddress((void**)&p_hwT, g_hwT);
    cudaGetSymbolAddress((void**)&p_wT, g_wT);
    cudaGetSymbolAddress((void**)&p_zwT, g_zwT);
    cudaGetSymbolAddress((void**)&p_dyh, g_dyh);
    cudaGetSymbolAddress((void**)&p_dyx, g_dyx);
    cudaGetSymbolAddress((void**)&p_dyb, g_dyb);
    cudaGetSymbolAddress((void**)&p_gates, g_gates);

    float* out_h1    = out;
    float* out_c1    = out + (size_t)NB * NH;
    float* out_hhat1 = out + (size_t)2 * NB * NH;
    float* out_chat1 = out + (size_t)2 * NB * NH + (size_t)NB * NZ;

    // 1. prep: concat + convert activations; transpose + convert weights
    concat_kernel<<<1024, 256>>>((const float4*)x, (const float4*)h0,
                                 (const float4*)hhat0, zb_h, zb_x);
    transpose_all<<<11456, 256>>>(hweight, weight, zw_h, zw_x, zw_b, dw_h, dw_x, dw_b);

    // 2. hyper GEMM: hg = hcat @ hweight + hbias  [2048,1024], K=2304
    tgemm<<<dim3(8, 16), 256, SMEM_TOT>>>(p_hcat, 2304, p_hwT, p_hg, 1024, 2304,
                                          hbias, nullptr, nullptr, nullptr, 0);

    // 3. hyper cell
    hyper_cell<<<(NB * NZ) / 256, 256>>>(chat0, out_hhat1, out_chat1);

    // 4. fused z GEMM: z = hhat1 @ zw_cat + zb_cat  [2048,768], K=256 (half out)
    tgemm<<<dim3(6, 16), 256, SMEM_TOT>>>(p_hhat1h, 256, p_zwT, p_z, 768, 256,
                                          p_zb, nullptr, nullptr, nullptr, 1);

    // 5. 12 modulation GEMMs, one launch  [2048,1024] each, K=64 (half out)
    mod_gemm<<<dim3(8, 16, 12), 256, SMEM_TOT>>>();

    // 6. main GEMM + fused modulation epilogue  [2048,4096], K=2048
    tgemm<<<dim3(32, 16), 256, SMEM_TOT>>>(p_cat2, 2048, p_wT, p_gates, 4096, 2048,
                                           bias, p_dyh, p_dyx, p_dyb, 0);

    // 7. main cell
    main_cell<<<(NB * NH) / 256, 256>>>(c0, out_h1, out_c1);
}

// round 6
// speedup vs baseline: 6.8735x; 1.0314x over previous
#include <cuda_runtime.h>
#include <cuda_fp16.h>
#include <cstdint>
#include <math.h>

// Problem dims
#define NB 2048
#define ND 1024
#define NH 1024
#define NZ 256
#define NE 64

// ---------------- scratch (static device globals; no allocation) ----------------
__device__ __align__(16) __half g_hcat[NB * (NZ + NH + ND)];  // [B,2304]
__device__ __align__(16) __half g_cat2[NB * (NH + ND)];       // [B,2048]
__device__ __align__(16) float  g_hg[NB * 4 * NZ];            // [B,1024]
__device__ __align__(16) __half g_hhat1h[NB * NZ];            // [B,256]
__device__ __align__(16) __half g_z[NB * 3 * 4 * NE];         // [B,768]
__device__ __align__(16) float  g_zbcat[768];
__device__ __align__(16) __half g_hwT[1024 * 2304];           // [N,K]
__device__ __align__(16) __half g_wT[4096 * 2048];            // [N,K]
__device__ __align__(16) __half g_zwT[768 * 256];             // [N,K]
__device__ __align__(16) __half g_dwT[12 * 1024 * 64];        // [w*4+g][N=1024][K=64]
__device__ __align__(16) float  g_gates[NB * 4 * NH];

__device__ __forceinline__ float sigf(float v) { return 1.f / (1.f + __expf(-v)); }

__device__ __forceinline__ uint32_t smem_u32(const void* p) {
    uint32_t a;
    asm("{ .reg .u64 t; cvta.to.shared.u64 t, %1; cvt.u32.u64 %0, t; }" : "=r"(a) : "l"(p));
    return a;
}
__device__ __forceinline__ void cpasync16(uint32_t saddr, const void* gaddr) {
    asm volatile("cp.async.cg.shared.global [%0], [%1], 16;" :: "r"(saddr), "l"(gaddr));
}

#define LDSM_X4(r, addr) \
    asm volatile("ldmatrix.sync.aligned.m8n8.x4.shared.b16 {%0,%1,%2,%3}, [%4];" \
        : "=r"((r)[0]), "=r"((r)[1]), "=r"((r)[2]), "=r"((r)[3]) : "r"(addr))

__device__ __forceinline__ void mma_f16(float* d, const uint32_t* a, const uint32_t* b) {
    asm volatile("mma.sync.aligned.m16n8k16.row.col.f32.f16.f16.f32 "
                 "{%0,%1,%2,%3}, {%4,%5,%6,%7}, {%8,%9}, {%0,%1,%2,%3};"
                 : "+f"(d[0]), "+f"(d[1]), "+f"(d[2]), "+f"(d[3])
                 : "r"(a[0]), "r"(a[1]), "r"(a[2]), "r"(a[3]), "r"(b[0]), "r"(b[1]));
}

__device__ __forceinline__ uint2 f4_to_h4(float4 v) {
    __half2 a = __floats2half2_rn(v.x, v.y);
    __half2 b = __floats2half2_rn(v.z, v.w);
    uint2 r;
    r.x = *reinterpret_cast<uint32_t*>(&a);
    r.y = *reinterpret_cast<uint32_t*>(&b);
    return r;
}

// ---------------- prep 1: concat + fp16 convert activations ----------------
__global__ void concat_kernel(const float4* __restrict__ x,
                              const float4* __restrict__ h0,
                              const float4* __restrict__ hhat0,
                              const float* __restrict__ zb_h,
                              const float* __restrict__ zb_x) {
    uint2* hc = reinterpret_cast<uint2*>(g_hcat);
    uint2* c2 = reinterpret_cast<uint2*>(g_cat2);
    const int HC4 = (NZ + NH + ND) / 4;  // 576
    const int N1 = NB * HC4;
    const int stride = gridDim.x * blockDim.x;
    const int t0 = blockIdx.x * blockDim.x + threadIdx.x;
    for (int i = t0; i < N1; i += stride) {
        int b = i / HC4;
        int c = i - b * HC4;
        float4 v;
        if (c < NZ / 4)                 v = hhat0[b * (NZ / 4) + c];
        else if (c < (NZ + NH) / 4)     v = h0[b * (NH / 4) + (c - NZ / 4)];
        else                            v = x[b * (ND / 4) + (c - (NZ + NH) / 4)];
        hc[i] = f4_to_h4(v);
    }
    const int N2 = NB * 512;
    for (int i = t0; i < N2; i += stride) {
        int b = i >> 9;
        int c = i & 511;
        float4 v = (c < 256) ? h0[b * 256 + c] : x[b * 256 + (c - 256)];
        c2[i] = f4_to_h4(v);
    }
    for (int i = t0; i < 768; i += stride)
        g_zbcat[i] = (i < 256) ? zb_h[i] : (i < 512) ? zb_x[i - 256] : 0.f;
}

// ---------------- prep 2: transpose + fp16 convert all weights ----------------
__global__ __launch_bounds__(256)
void transpose_all(const float* __restrict__ hw, const float* __restrict__ w,
                   const float* __restrict__ zh, const float* __restrict__ zx,
                   const float* __restrict__ zb,
                   const float* __restrict__ dh, const float* __restrict__ dx,
                   const float* __restrict__ db) {
    __shared__ float t[32][33];
    int b = blockIdx.x;
    const float* in; __half* out; int K, N, lt;
    if (b < 2304)       { in = hw; out = g_hwT; K = 2304; N = 1024; lt = b; }
    else if (b < 10496) { in = w;  out = g_wT;  K = 2048; N = 4096; lt = b - 2304; }
    else if (b < 10688) {
        int i = (b - 10496) >> 6;  // 0..2
        in = (i == 0 ? zh : i == 1 ? zx : zb);
        out = g_zwT + i * 256 * 256;
        K = 256; N = 256; lt = (b - 10496) & 63;
    } else {
        int i = (b - 10688) >> 6;  // 0..11
        int wsel = i / 4, g = i & 3;
        in = (wsel == 0 ? dh : wsel == 1 ? dx : db) + (size_t)g * 64 * 1024;
        out = g_dwT + (size_t)i * 1024 * 64;
        K = 64; N = 1024; lt = (b - 10688) & 63;
    }
    const int ntx = N >> 5;
    const int tx = lt % ntx, ty = lt / ntx;
    const int lx = threadIdx.x & 31, ly = threadIdx.x >> 5;
#pragma unroll
    for (int j = 0; j < 4; j++) {
        int k = ly + j * 8;
        t[k][lx] = in[(size_t)(ty * 32 + k) * N + tx * 32 + lx];
    }
    __syncthreads();
#pragma unroll
    for (int j = 0; j < 4; j++) {
        int r = ly + j * 8;  // n within tile
        out[(size_t)(tx * 32 + r) * K + ty * 32 + lx] = __float2half_rn(t[lx][r]);
    }
}

// ---------------- shared GEMM geometry ----------------
#define SLDH 72                       // smem row stride in halfs (144B), LDSM conflict-free
#define TILE_B (128 * SLDH * 2)       // 18432 bytes per operand tile
#define STAGE_B (2 * TILE_B)          // 36864 per stage
#define SMEM_TOT (2 * STAGE_B)        // 73728

// ---------------- generic fp16 GEMM (bias epilogue) ----------------
__global__ __launch_bounds__(256, 2)
void tgemm(const __half* __restrict__ A, int lda,
           const __half* __restrict__ Wt,
           void* __restrict__ Cv, int ldc, int K,
           const float* __restrict__ bias, int out_half) {
    extern __shared__ __align__(16) char dynsmem[];
    const uint32_t sbase = smem_u32(dynsmem);
    const int tid = threadIdx.x;
    const int lane = tid & 31;
    const int wid = tid >> 5;
    const int wm = (wid & 1) << 6;
    const int wn = (wid >> 1) << 5;
    const int bM = blockIdx.y * 128;
    const int bN = blockIdx.x * 128;

    float acc[4][4][4];
#pragma unroll
    for (int i = 0; i < 4; i++)
#pragma unroll
        for (int j = 0; j < 4; j++)
#pragma unroll
            for (int q = 0; q < 4; q++) acc[i][j][q] = 0.f;

    const int jj = lane >> 3;
    const int l7 = lane & 7;
    const uint32_t a_off = (uint32_t)((wm + ((jj & 1) << 3) + l7) * (SLDH * 2) + ((jj >> 1) << 4));
    const uint32_t b_off = (uint32_t)((wn + ((jj >> 1) << 3) + l7) * (SLDH * 2) + ((jj & 1) << 4));

    const int r_ld = tid >> 3;
    const int c8 = tid & 7;

    const __half* Arow = A + (size_t)bM * lda;
    const __half* Brow = Wt + (size_t)bN * K;

#define ISSUE(c_, st_) do { \
    uint32_t sa = sbase + (st_) * STAGE_B; \
    uint32_t sb = sa + TILE_B; \
    int k0 = (c_) << 6; \
    _Pragma("unroll") \
    for (int i = 0; i < 4; i++) { \
        int r = r_ld + (i << 5); \
        uint32_t so = (uint32_t)(r * (SLDH * 2) + (c8 << 4)); \
        cpasync16(sa + so, Arow + (size_t)r * lda + k0 + (c8 << 3)); \
        cpasync16(sb + so, Brow + (size_t)r * K + k0 + (c8 << 3)); \
    } \
    asm volatile("cp.async.commit_group;" ::: "memory"); \
} while (0)

    const int nch = K >> 6;
    ISSUE(0, 0);
    for (int c = 0; c < nch; c++) {
        if (c + 1 < nch) {
            ISSUE(c + 1, (c + 1) & 1);
            asm volatile("cp.async.wait_group 1;" ::: "memory");
        } else {
            asm volatile("cp.async.wait_group 0;" ::: "memory");
        }
        __syncthreads();
        const uint32_t a_base = sbase + (c & 1) * STAGE_B;
        const uint32_t b_base = a_base + TILE_B;
#pragma unroll
        for (int ks = 0; ks < 4; ks++) {
            const uint32_t kb = (uint32_t)(ks << 5);
            uint32_t af[4][4], bf[2][4];
#pragma unroll
            for (int mf = 0; mf < 4; mf++)
                LDSM_X4(af[mf], a_base + a_off + (uint32_t)(mf * 16 * SLDH * 2) + kb);
#pragma unroll
            for (int p = 0; p < 2; p++)
                LDSM_X4(bf[p], b_base + b_off + (uint32_t)(p * 16 * SLDH * 2) + kb);
#pragma unroll
            for (int mf = 0; mf < 4; mf++)
#pragma unroll
                for (int nf = 0; nf < 4; nf++)
                    mma_f16(acc[mf][nf], af[mf], bf[nf >> 1] + ((nf & 1) << 1));
        }
        __syncthreads();
    }
#undef ISSUE

    const int r0 = bM + wm + (lane >> 2);
    const int c0 = bN + wn + ((lane & 3) << 1);
#pragma unroll
    for (int mf = 0; mf < 4; mf++) {
#pragma unroll
        for (int half = 0; half < 2; half++) {
            const int row = r0 + mf * 16 + half * 8;
#pragma unroll
            for (int nf = 0; nf < 4; nf++) {
                const int col = c0 + nf * 8;
                float2 v;
                v.x = acc[mf][nf][half * 2 + 0];
                v.y = acc[mf][nf][half * 2 + 1];
                if (bias) {
                    float2 bb = *reinterpret_cast<const float2*>(bias + col);
                    v.x += bb.x;
                    v.y += bb.y;
                }
                if (out_half) {
                    __half* Ch = reinterpret_cast<__half*>(Cv) + (size_t)row * ldc + col;
                    *reinterpret_cast<__half2*>(Ch) = __floats2half2_rn(v.x, v.y);
                } else {
                    float* Cf = reinterpret_cast<float*>(Cv) + (size_t)row * ldc + col;
                    *reinterpret_cast<float2*>(Cf) = v;
                }
            }
        }
    }
}

// ---------------- main GEMM with fully fused modulation (dy via in-kernel MMA) ----------------
__global__ __launch_bounds__(256, 2)
void main_gemm(const float* __restrict__ bias) {
    extern __shared__ __align__(16) char dynsmem[];
    const uint32_t sbase = smem_u32(dynsmem);
    const int tid = threadIdx.x;
    const int lane = tid & 31;
    const int wid = tid >> 5;
    const int wm = (wid & 1) << 6;
    const int wn = (wid >> 1) << 5;
    const int bM = blockIdx.y * 128;
    const int bN = blockIdx.x * 128;
    const int g = bN >> 10;          // gate index (tile lies in one gate)
    const int hcol = bN & 1023;

    float acc[4][4][4];
#pragma unroll
    for (int i = 0; i < 4; i++)
#pragma unroll
        for (int j = 0; j < 4; j++)
#pragma unroll
            for (int q = 0; q < 4; q++) acc[i][j][q] = 0.f;

    const int jj = lane >> 3;
    const int l7 = lane & 7;
    const uint32_t a_off = (uint32_t)((wm + ((jj & 1) << 3) + l7) * (SLDH * 2) + ((jj >> 1) << 4));
    const uint32_t b_off = (uint32_t)((wn + ((jj >> 1) << 3) + l7) * (SLDH * 2) + ((jj & 1) << 4));

    const int r_ld = tid >> 3;
    const int c8 = tid & 7;

    const __half* Arow = g_cat2 + (size_t)bM * 2048;
    const __half* Brow = g_wT + (size_t)bN * 2048;

#define ISSUE(c_, st_) do { \
    uint32_t sa = sbase + (st_) * STAGE_B; \
    uint32_t sb = sa + TILE_B; \
    int k0 = (c_) << 6; \
    _Pragma("unroll") \
    for (int i = 0; i < 4; i++) { \
        int r = r_ld + (i << 5); \
        uint32_t so = (uint32_t)(r * (SLDH * 2) + (c8 << 4)); \
        cpasync16(sa + so, Arow + (size_t)r * 2048 + k0 + (c8 << 3)); \
        cpasync16(sb + so, Brow + (size_t)r * 2048 + k0 + (c8 << 3)); \
    } \
    asm volatile("cp.async.commit_group;" ::: "memory"); \
} while (0)

    const int nch = 2048 >> 6;  // 32
    ISSUE(0, 0);
    for (int c = 0; c < nch; c++) {
        if (c + 1 < nch) {
            ISSUE(c + 1, (c + 1) & 1);
            asm volatile("cp.async.wait_group 1;" ::: "memory");
        } else {
            asm volatile("cp.async.wait_group 0;" ::: "memory");
        }
        __syncthreads();
        const uint32_t a_base = sbase + (c & 1) * STAGE_B;
        const uint32_t b_base = a_base + TILE_B;
#pragma unroll
        for (int ks = 0; ks < 4; ks++) {
            const uint32_t kb = (uint32_t)(ks << 5);
            uint32_t af[4][4], bf[2][4];
#pragma unroll
            for (int mf = 0; mf < 4; mf++)
                LDSM_X4(af[mf], a_base + a_off + (uint32_t)(mf * 16 * SLDH * 2) + kb);
#pragma unroll
            for (int p = 0; p < 2; p++)
                LDSM_X4(bf[p], b_base + b_off + (uint32_t)(p * 16 * SLDH * 2) + kb);
#pragma unroll
            for (int mf = 0; mf < 4; mf++)
#pragma unroll
                for (int nf = 0; nf < 4; nf++)
                    mma_f16(acc[mf][nf], af[mf], bf[nf >> 1] + ((nf & 1) << 1));
        }
        __syncthreads();
    }
#undef ISSUE

    // ---- fused modulation: 3 K=64 MMA chains (dyh, dyx, dyb) ----
    // A slice: z[bM.., t*256 + g*64 ..+64] stride 768; B slice: dwT[t*4+g][hcol..][64]
    const __half* zb0 = g_z + (size_t)bM * 768 + g * 64;
    const __half* dw0 = g_dwT + (size_t)g * 65536 + (size_t)hcol * 64;

#define ISSUE_DY(t_, st_) do { \
    const __half* zp = zb0 + (t_) * 256; \
    const __half* dp = dw0 + (size_t)(t_) * 4 * 65536; \
    uint32_t sa = sbase + (st_) * STAGE_B; \
    uint32_t sb = sa + TILE_B; \
    _Pragma("unroll") \
    for (int i = 0; i < 4; i++) { \
        int idx = tid + (i << 8); \
        int r = idx >> 3, ch = idx & 7; \
        uint32_t so = (uint32_t)(r * (SLDH * 2) + (ch << 4)); \
        cpasync16(sa + so, zp + (size_t)r * 768 + (ch << 3)); \
        cpasync16(sb + so, dp + r * 64 + (ch << 3)); \
    } \
    asm volatile("cp.async.commit_group;" ::: "memory"); \
} while (0)

#define DY_CHAIN(st_, is_add_) do { \
    const uint32_t a_base = sbase + (st_) * STAGE_B; \
    const uint32_t b_base = a_base + TILE_B; \
    _Pragma("unroll") \
    for (int np = 0; np < 2; np++) { \
        float dacc[4][2][4]; \
        _Pragma("unroll") \
        for (int mf = 0; mf < 4; mf++) \
            _Pragma("unroll") \
            for (int j = 0; j < 2; j++) \
                _Pragma("unroll") \
                for (int q = 0; q < 4; q++) dacc[mf][j][q] = 0.f; \
        _Pragma("unroll") \
        for (int ks = 0; ks < 4; ks++) { \
            const uint32_t kb = (uint32_t)(ks << 5); \
            uint32_t af[4][4], bf[4]; \
            _Pragma("unroll") \
            for (int mf = 0; mf < 4; mf++) \
                LDSM_X4(af[mf], a_base + a_off + (uint32_t)(mf * 16 * SLDH * 2) + kb); \
            LDSM_X4(bf, b_base + b_off + (uint32_t)(np * 16 * SLDH * 2) + kb); \
            _Pragma("unroll") \
            for (int mf = 0; mf < 4; mf++) \
                _Pragma("unroll") \
                for (int j = 0; j < 2; j++) \
                    mma_f16(dacc[mf][j], af[mf], bf + (j << 1)); \
        } \
        _Pragma("unroll") \
        for (int mf = 0; mf < 4; mf++) \
            _Pragma("unroll") \
            for (int j = 0; j < 2; j++) \
                _Pragma("unroll") \
                for (int q = 0; q < 4; q++) { \
                    if (is_add_) acc[mf][np * 2 + j][q] += dacc[mf][j][q]; \
                    else         acc[mf][np * 2 + j][q] *= dacc[mf][j][q]; \
                } \
    } \
} while (0)

    ISSUE_DY(0, 0);
    ISSUE_DY(1, 1);
    asm volatile("cp.async.wait_group 1;" ::: "memory");
    __syncthreads();
    DY_CHAIN(0, 0);          // acc *= dyh
    __syncthreads();
    ISSUE_DY(2, 0);
    asm volatile("cp.async.wait_group 1;" ::: "memory");
    __syncthreads();
    DY_CHAIN(1, 0);          // acc *= dyx
    asm volatile("cp.async.wait_group 0;" ::: "memory");
    __syncthreads();
    DY_CHAIN(0, 1);          // acc += dyb
#undef ISSUE_DY
#undef DY_CHAIN

    // ---- epilogue: + bias, write f32 gates ----
    const int r0 = bM + wm + (lane >> 2);
    const int c0 = bN + wn + ((lane & 3) << 1);
#pragma unroll
    for (int mf = 0; mf < 4; mf++) {
#pragma unroll
        for (int half = 0; half < 2; half++) {
            const int row = r0 + mf * 16 + half * 8;
            float* Cf = g_gates + (size_t)row * 4096;
#pragma unroll
            for (int nf = 0; nf < 4; nf++) {
                const int col = c0 + nf * 8;
                float2 v;
                v.x = acc[mf][nf][half * 2 + 0] + bias[col];
                v.y = acc[mf][nf][half * 2 + 1] + bias[col + 1];
                *reinterpret_cast<float2*>(Cf + col) = v;
            }
        }
    }
}

// ---------------- elementwise cells ----------------
__global__ void hyper_cell(const float* __restrict__ chat0,
                           float* __restrict__ out_hhat1,
                           float* __restrict__ out_chat1) {
    int idx = blockIdx.x * blockDim.x + threadIdx.x;
    if (idx >= NB * NZ) return;
    int b = idx >> 8;
    int z = idx & (NZ - 1);
    const float* row = g_hg + (size_t)b * (4 * NZ);
    float iv = row[z], gv = row[NZ + z], fv = row[2 * NZ + z], ov = row[3 * NZ + z];
    float c1 = sigf(fv) * chat0[idx] + sigf(iv) * tanhf(gv);
    float h1 = sigf(ov) * tanhf(c1);
    out_chat1[idx] = c1;
    out_hhat1[idx] = h1;
    g_hhat1h[idx] = __float2half_rn(h1);
}

__global__ void main_cell(const float* __restrict__ c0,
                          float* __restrict__ out_h1,
                          float* __restrict__ out_c1) {
    int idx = blockIdx.x * blockDim.x + threadIdx.x;
    if (idx >= NB * NH) return;
    int b = idx >> 10;
    int h = idx & (NH - 1);
    const float* row = g_gates + (size_t)b * (4 * NH);
    float iv = row[h], gv = row[NH + h], fv = row[2 * NH + h], ov = row[3 * NH + h];
    float c1 = sigf(fv) * c0[idx] + sigf(iv) * tanhf(gv);
    out_c1[idx] = c1;
    out_h1[idx] = sigf(ov) * tanhf(c1);
}

// ---------------- launch ----------------
extern "C" void kernel_launch(void* const* d_in, const int* in_sizes, int n_in,
                              void* d_out, int out_size) {
    const float* x       = (const float*)d_in[0];
    const float* h0      = (const float*)d_in[1];
    const float* c0      = (const float*)d_in[2];
    const float* hhat0   = (const float*)d_in[3];
    const float* chat0   = (const float*)d_in[4];
    const float* hweight = (const float*)d_in[5];
    const float* hbias   = (const float*)d_in[6];
    const float* zw_h    = (const float*)d_in[7];
    const float* zw_x    = (const float*)d_in[8];
    const float* zw_b    = (const float*)d_in[9];
    const float* zb_h    = (const float*)d_in[10];
    const float* zb_x    = (const float*)d_in[11];
    const float* dw_h    = (const float*)d_in[12];
    const float* dw_x    = (const float*)d_in[13];
    const float* dw_b    = (const float*)d_in[14];
    const float* weight  = (const float*)d_in[15];
    const float* bias    = (const float*)d_in[16];
    float* out = (float*)d_out;

    static int smem_set = 0;
    if (!smem_set) {
        cudaFuncSetAttribute(tgemm, cudaFuncAttributeMaxDynamicSharedMemorySize, SMEM_TOT);
        cudaFuncSetAttribute(main_gemm, cudaFuncAttributeMaxDynamicSharedMemorySize, SMEM_TOT);
        smem_set = 1;
    }

    __half *p_hcat, *p_hhat1h, *p_z, *p_hwT, *p_zwT;
    float *p_hg, *p_zb;
    cudaGetSymbolAddress((void**)&p_hcat, g_hcat);
    cudaGetSymbolAddress((void**)&p_hg, g_hg);
    cudaGetSymbolAddress((void**)&p_hhat1h, g_hhat1h);
    cudaGetSymbolAddress((void**)&p_z, g_z);
    cudaGetSymbolAddress((void**)&p_zb, g_zbcat);
    cudaGetSymbolAddress((void**)&p_hwT, g_hwT);
    cudaGetSymbolAddress((void**)&p_zwT, g_zwT);

    float* out_h1    = out;
    float* out_c1    = out + (size_t)NB * NH;
    float* out_hhat1 = out + (size_t)2 * NB * NH;
    float* out_chat1 = out + (size_t)2 * NB * NH + (size_t)NB * NZ;

    // 1. prep: concat + convert activations; transpose + convert weights
    concat_kernel<<<1024, 256>>>((const float4*)x, (const float4*)h0,
                                 (const float4*)hhat0, zb_h, zb_x);
    transpose_all<<<11456, 256>>>(hweight, weight, zw_h, zw_x, zw_b, dw_h, dw_x, dw_b);

    // 2. hyper GEMM: hg = hcat @ hweight + hbias  [2048,1024], K=2304
    tgemm<<<dim3(8, 16), 256, SMEM_TOT>>>(p_hcat, 2304, p_hwT, p_hg, 1024, 2304,
                                          hbias, 0);

    // 3. hyper cell
    hyper_cell<<<(NB * NZ) / 256, 256>>>(chat0, out_hhat1, out_chat1);

    // 4. fused z GEMM: z = hhat1 @ zw_cat + zb_cat  [2048,768], K=256 (half out)
    tgemm<<<dim3(6, 16), 256, SMEM_TOT>>>(p_hhat1h, 256, p_zwT, p_z, 768, 256,
                                          p_zb, 1);

    // 5. main GEMM with fused modulation  [2048,4096], K=2048
    main_gemm<<<dim3(32, 16), 256, SMEM_TOT>>>(bias);

    // 6. main cell
    main_cell<<<(NB * NH) / 256, 256>>>(c0, out_h1, out_c1);
}

// round 7
// speedup vs baseline: 7.0804x; 1.0301x over previous
#include <cuda_runtime.h>
#include <cuda_fp16.h>
#include <cstdint>
#include <math.h>

// Problem dims
#define NB 2048
#define ND 1024
#define NH 1024
#define NZ 256
#define NE 64

// ---------------- scratch (static device globals; no allocation) ----------------
__device__ __align__(16) __half g_hcat[NB * (NZ + NH + ND)];  // [B,2304]
__device__ __align__(16) __half g_cat2[NB * (NH + ND)];       // [B,2048]
__device__ __align__(16) float  g_hgp[2 * NB * 4 * NZ];       // split-K partials
__device__ __align__(16) __half g_hhat1h[NB * NZ];            // [B,256]
__device__ __align__(16) __half g_z[NB * 3 * 4 * NE];         // [B,768]
__device__ __align__(16) float  g_zbcat[768];
__device__ __align__(16) __half g_hwT[1024 * 2304];           // [N,K]
__device__ __align__(16) __half g_wT[4096 * 2048];            // [N,K]
__device__ __align__(16) __half g_zwT[768 * 256];             // [N,K]
__device__ __align__(16) __half g_dwT[12 * 1024 * 64];        // [w*4+g][N=1024][K=64]
__device__ __align__(16) float  g_gates[NB * 4 * NH];

__device__ __forceinline__ float sigf(float v) { return 1.f / (1.f + __expf(-v)); }

__device__ __forceinline__ uint32_t smem_u32(const void* p) {
    uint32_t a;
    asm("{ .reg .u64 t; cvta.to.shared.u64 t, %1; cvt.u32.u64 %0, t; }" : "=r"(a) : "l"(p));
    return a;
}
__device__ __forceinline__ void cpasync16(uint32_t saddr, const void* gaddr) {
    asm volatile("cp.async.cg.shared.global [%0], [%1], 16;" :: "r"(saddr), "l"(gaddr));
}
#define COMMIT() asm volatile("cp.async.commit_group;" ::: "memory")
#define WAITG0() asm volatile("cp.async.wait_group 0;" ::: "memory")
#define WAITG1() asm volatile("cp.async.wait_group 1;" ::: "memory")
#define WAITG2() asm volatile("cp.async.wait_group 2;" ::: "memory")

#define LDSM_X4(r, addr) \
    asm volatile("ldmatrix.sync.aligned.m8n8.x4.shared.b16 {%0,%1,%2,%3}, [%4];" \
        : "=r"((r)[0]), "=r"((r)[1]), "=r"((r)[2]), "=r"((r)[3]) : "r"(addr))

__device__ __forceinline__ void mma_f16(float* d, const uint32_t* a, const uint32_t* b) {
    asm volatile("mma.sync.aligned.m16n8k16.row.col.f32.f16.f16.f32 "
                 "{%0,%1,%2,%3}, {%4,%5,%6,%7}, {%8,%9}, {%0,%1,%2,%3};"
                 : "+f"(d[0]), "+f"(d[1]), "+f"(d[2]), "+f"(d[3])
                 : "r"(a[0]), "r"(a[1]), "r"(a[2]), "r"(a[3]), "r"(b[0]), "r"(b[1]));
}

__device__ __forceinline__ uint2 f4_to_h4(float4 v) {
    __half2 a = __floats2half2_rn(v.x, v.y);
    __half2 b = __floats2half2_rn(v.z, v.w);
    uint2 r;
    r.x = *reinterpret_cast<uint32_t*>(&a);
    r.y = *reinterpret_cast<uint32_t*>(&b);
    return r;
}

// ---------------- prep: concat + transpose, one launch ----------------
// blocks [0,1024): concat; blocks [1024,12480): weight transposes
__global__ __launch_bounds__(256)
void prep_all(const float4* __restrict__ x, const float4* __restrict__ h0,
              const float4* __restrict__ hhat0,
              const float* __restrict__ zb_h, const float* __restrict__ zb_x,
              const float* __restrict__ hw, const float* __restrict__ w,
              const float* __restrict__ zh, const float* __restrict__ zx,
              const float* __restrict__ zb,
              const float* __restrict__ dh, const float* __restrict__ dx,
              const float* __restrict__ db) {
    __shared__ float t[32][33];
    if (blockIdx.x < 1024) {
        uint2* hc = reinterpret_cast<uint2*>(g_hcat);
        uint2* c2 = reinterpret_cast<uint2*>(g_cat2);
        const int HC4 = (NZ + NH + ND) / 4;  // 576
        const int N1 = NB * HC4;
        const int stride = 1024 * 256;
        const int t0 = blockIdx.x * 256 + threadIdx.x;
        for (int i = t0; i < N1; i += stride) {
            int b = i / HC4;
            int c = i - b * HC4;
            float4 v;
            if (c < NZ / 4)                 v = hhat0[b * (NZ / 4) + c];
            else if (c < (NZ + NH) / 4)     v = h0[b * (NH / 4) + (c - NZ / 4)];
            else                            v = x[b * (ND / 4) + (c - (NZ + NH) / 4)];
            hc[i] = f4_to_h4(v);
        }
        const int N2 = NB * 512;
        for (int i = t0; i < N2; i += stride) {
            int b = i >> 9;
            int c = i & 511;
            float4 v = (c < 256) ? h0[b * 256 + c] : x[b * 256 + (c - 256)];
            c2[i] = f4_to_h4(v);
        }
        for (int i = t0; i < 768; i += stride)
            g_zbcat[i] = (i < 256) ? zb_h[i] : (i < 512) ? zb_x[i - 256] : 0.f;
        return;
    }
    int b = blockIdx.x - 1024;
    const float* in; __half* out; int K, N, lt;
    if (b < 2304)       { in = hw; out = g_hwT; K = 2304; N = 1024; lt = b; }
    else if (b < 10496) { in = w;  out = g_wT;  K = 2048; N = 4096; lt = b - 2304; }
    else if (b < 10688) {
        int i = (b - 10496) >> 6;
        in = (i == 0 ? zh : i == 1 ? zx : zb);
        out = g_zwT + i * 256 * 256;
        K = 256; N = 256; lt = (b - 10496) & 63;
    } else {
        int i = (b - 10688) >> 6;
        int wsel = i / 4, g = i & 3;
        in = (wsel == 0 ? dh : wsel == 1 ? dx : db) + (size_t)g * 64 * 1024;
        out = g_dwT + (size_t)i * 1024 * 64;
        K = 64; N = 1024; lt = (b - 10688) & 63;
    }
    const int ntx = N >> 5;
    const int tx = lt % ntx, ty = lt / ntx;
    const int lx = threadIdx.x & 31, ly = threadIdx.x >> 5;
#pragma unroll
    for (int j = 0; j < 4; j++) {
        int k = ly + j * 8;
        t[k][lx] = in[(size_t)(ty * 32 + k) * N + tx * 32 + lx];
    }
    __syncthreads();
#pragma unroll
    for (int j = 0; j < 4; j++) {
        int r = ly + j * 8;
        out[(size_t)(tx * 32 + r) * K + ty * 32 + lx] = __float2half_rn(t[lx][r]);
    }
}

// ---------------- shared GEMM geometry ----------------
#define SLDH 72                       // smem row stride in halfs (144B)
#define TILE_B (128 * SLDH * 2)       // 18432 bytes per operand tile
#define STAGE_B (2 * TILE_B)          // 36864 per stage
#define SMEM_TOT (3 * STAGE_B)        // 110592, 3 stages

// ---------------- fp16 GEMM core: 128x128 tile, BK=64, 3-stage cp.async ----------------
__device__ __forceinline__ void gemm_core(
    const __half* __restrict__ A, int lda,
    const __half* __restrict__ Wt, int ldw,
    void* __restrict__ Cv, int ldc, int K,
    const float* __restrict__ bias, int out_half,
    int bM, int bN) {
    extern __shared__ __align__(16) char dynsmem[];
    const uint32_t sbase = smem_u32(dynsmem);
    const int tid = threadIdx.x;
    const int lane = tid & 31;
    const int wid = tid >> 5;
    const int wm = (wid & 1) << 6;
    const int wn = (wid >> 1) << 5;

    float acc[4][4][4];
#pragma unroll
    for (int i = 0; i < 4; i++)
#pragma unroll
        for (int j = 0; j < 4; j++)
#pragma unroll
            for (int q = 0; q < 4; q++) acc[i][j][q] = 0.f;

    const int jj = lane >> 3;
    const int l7 = lane & 7;
    const uint32_t a_off = (uint32_t)((wm + ((jj & 1) << 3) + l7) * (SLDH * 2) + ((jj >> 1) << 4));
    const uint32_t b_off = (uint32_t)((wn + ((jj >> 1) << 3) + l7) * (SLDH * 2) + ((jj & 1) << 4));

    const int r_ld = tid >> 3;
    const int c8 = tid & 7;

    const __half* Arow = A + (size_t)bM * lda;
    const __half* Brow = Wt + (size_t)bN * ldw;

#define ISSUE(c_, st_) do { \
    uint32_t sa = sbase + (st_) * STAGE_B; \
    uint32_t sb = sa + TILE_B; \
    int k0 = (c_) << 6; \
    _Pragma("unroll") \
    for (int i = 0; i < 4; i++) { \
        int r = r_ld + (i << 5); \
        uint32_t so = (uint32_t)(r * (SLDH * 2) + (c8 << 4)); \
        cpasync16(sa + so, Arow + (size_t)r * lda + k0 + (c8 << 3)); \
        cpasync16(sb + so, Brow + (size_t)r * ldw + k0 + (c8 << 3)); \
    } \
    COMMIT(); \
} while (0)

    const int nch = K >> 6;
    ISSUE(0, 0);
    if (nch > 1) ISSUE(1, 1);
    for (int c = 0; c < nch; c++) {
        if (c + 2 < nch) { ISSUE(c + 2, (c + 2) % 3); WAITG2(); }
        else if (c + 1 < nch) WAITG1();
        else WAITG0();
        __syncthreads();
        const uint32_t a_base = sbase + (c % 3) * STAGE_B;
        const uint32_t b_base = a_base + TILE_B;
#pragma unroll
        for (int ks = 0; ks < 4; ks++) {
            const uint32_t kb = (uint32_t)(ks << 5);
            uint32_t af[4][4], bf[2][4];
#pragma unroll
            for (int mf = 0; mf < 4; mf++)
                LDSM_X4(af[mf], a_base + a_off + (uint32_t)(mf * 16 * SLDH * 2) + kb);
#pragma unroll
            for (int p = 0; p < 2; p++)
                LDSM_X4(bf[p], b_base + b_off + (uint32_t)(p * 16 * SLDH * 2) + kb);
#pragma unroll
            for (int mf = 0; mf < 4; mf++)
#pragma unroll
                for (int nf = 0; nf < 4; nf++)
                    mma_f16(acc[mf][nf], af[mf], bf[nf >> 1] + ((nf & 1) << 1));
        }
        __syncthreads();
    }
#undef ISSUE

    const int r0 = bM + wm + (lane >> 2);
    const int c0 = bN + wn + ((lane & 3) << 1);
#pragma unroll
    for (int mf = 0; mf < 4; mf++) {
#pragma unroll
        for (int half = 0; half < 2; half++) {
            const int row = r0 + mf * 16 + half * 8;
#pragma unroll
            for (int nf = 0; nf < 4; nf++) {
                const int col = c0 + nf * 8;
                float2 v;
                v.x = acc[mf][nf][half * 2 + 0];
                v.y = acc[mf][nf][half * 2 + 1];
                if (bias) {
                    float2 bb = *reinterpret_cast<const float2*>(bias + col);
                    v.x += bb.x;
                    v.y += bb.y;
                }
                if (out_half) {
                    __half* Ch = reinterpret_cast<__half*>(Cv) + (size_t)row * ldc + col;
                    *reinterpret_cast<__half2*>(Ch) = __floats2half2_rn(v.x, v.y);
                } else {
                    float* Cf = reinterpret_cast<float*>(Cv) + (size_t)row * ldc + col;
                    *reinterpret_cast<float2*>(Cf) = v;
                }
            }
        }
    }
}

// hyper GEMM, split-K=2: z = blockIdx.z selects K-half and partial buffer
__global__ __launch_bounds__(256, 2)
void hyper_gemm() {
    const int z = blockIdx.z;
    gemm_core(g_hcat + z * 1152, 2304, g_hwT + z * 1152, 2304,
              g_hgp + (size_t)z * NB * 1024, 1024, 1152, nullptr, 0,
              blockIdx.y * 128, blockIdx.x * 128);
}

// z GEMM: z = hhat1 @ zw_cat + zb_cat (half out)
__global__ __launch_bounds__(256, 2)
void z_gemm() {
    gemm_core(g_hhat1h, 256, g_zwT, 256, g_z, 768, 256, g_zbcat, 1,
              blockIdx.y * 128, blockIdx.x * 128);
}

// ---------------- main GEMM with fused modulation ----------------
__global__ __launch_bounds__(256, 2)
void main_gemm(const float* __restrict__ bias) {
    extern __shared__ __align__(16) char dynsmem[];
    const uint32_t sbase = smem_u32(dynsmem);
    const int tid = threadIdx.x;
    const int lane = tid & 31;
    const int wid = tid >> 5;
    const int wm = (wid & 1) << 6;
    const int wn = (wid >> 1) << 5;
    const int bM = blockIdx.y * 128;
    const int bN = blockIdx.x * 128;
    const int g = bN >> 10;
    const int hcol = bN & 1023;

    float acc[4][4][4];
#pragma unroll
    for (int i = 0; i < 4; i++)
#pragma unroll
        for (int j = 0; j < 4; j++)
#pragma unroll
            for (int q = 0; q < 4; q++) acc[i][j][q] = 0.f;

    const int jj = lane >> 3;
    const int l7 = lane & 7;
    const uint32_t a_off = (uint32_t)((wm + ((jj & 1) << 3) + l7) * (SLDH * 2) + ((jj >> 1) << 4));
    const uint32_t b_off = (uint32_t)((wn + ((jj >> 1) << 3) + l7) * (SLDH * 2) + ((jj & 1) << 4));

    const int r_ld = tid >> 3;
    const int c8 = tid & 7;

    const __half* Arow = g_cat2 + (size_t)bM * 2048;
    const __half* Brow = g_wT + (size_t)bN * 2048;

#define ISSUE(c_, st_) do { \
    uint32_t sa = sbase + (st_) * STAGE_B; \
    uint32_t sb = sa + TILE_B; \
    int k0 = (c_) << 6; \
    _Pragma("unroll") \
    for (int i = 0; i < 4; i++) { \
        int r = r_ld + (i << 5); \
        uint32_t so = (uint32_t)(r * (SLDH * 2) + (c8 << 4)); \
        cpasync16(sa + so, Arow + (size_t)r * 2048 + k0 + (c8 << 3)); \
        cpasync16(sb + so, Brow + (size_t)r * 2048 + k0 + (c8 << 3)); \
    } \
    COMMIT(); \
} while (0)

    const int nch = 32;
    ISSUE(0, 0);
    ISSUE(1, 1);
    for (int c = 0; c < nch; c++) {
        if (c + 2 < nch) { ISSUE(c + 2, (c + 2) % 3); WAITG2(); }
        else if (c + 1 < nch) WAITG1();
        else WAITG0();
        __syncthreads();
        const uint32_t a_base = sbase + (c % 3) * STAGE_B;
        const uint32_t b_base = a_base + TILE_B;
#pragma unroll
        for (int ks = 0; ks < 4; ks++) {
            const uint32_t kb = (uint32_t)(ks << 5);
            uint32_t af[4][4], bf[2][4];
#pragma unroll
            for (int mf = 0; mf < 4; mf++)
                LDSM_X4(af[mf], a_base + a_off + (uint32_t)(mf * 16 * SLDH * 2) + kb);
#pragma unroll
            for (int p = 0; p < 2; p++)
                LDSM_X4(bf[p], b_base + b_off + (uint32_t)(p * 16 * SLDH * 2) + kb);
#pragma unroll
            for (int mf = 0; mf < 4; mf++)
#pragma unroll
                for (int nf = 0; nf < 4; nf++)
                    mma_f16(acc[mf][nf], af[mf], bf[nf >> 1] + ((nf & 1) << 1));
        }
        __syncthreads();
    }
#undef ISSUE

    // ---- fused modulation: 3 K=64 MMA chains (dyh, dyx, dyb), fully prefetched ----
    const __half* zb0 = g_z + (size_t)bM * 768 + g * 64;
    const __half* dw0 = g_dwT + (size_t)g * 65536 + (size_t)hcol * 64;

#define ISSUE_DY(t_, st_) do { \
    const __half* zp = zb0 + (t_) * 256; \
    const __half* dp = dw0 + (size_t)(t_) * 4 * 65536; \
    uint32_t sa = sbase + (st_) * STAGE_B; \
    uint32_t sb = sa + TILE_B; \
    _Pragma("unroll") \
    for (int i = 0; i < 4; i++) { \
        int idx = tid + (i << 8); \
        int r = idx >> 3, ch = idx & 7; \
        uint32_t so = (uint32_t)(r * (SLDH * 2) + (ch << 4)); \
        cpasync16(sa + so, zp + (size_t)r * 768 + (ch << 3)); \
        cpasync16(sb + so, dp + r * 64 + (ch << 3)); \
    } \
    COMMIT(); \
} while (0)

#define DY_CHAIN(st_, is_add_) do { \
    const uint32_t a_base = sbase + (st_) * STAGE_B; \
    const uint32_t b_base = a_base + TILE_B; \
    _Pragma("unroll") \
    for (int np = 0; np < 2; np++) { \
        float dacc[4][2][4]; \
        _Pragma("unroll") \
        for (int mf = 0; mf < 4; mf++) \
            _Pragma("unroll") \
            for (int j = 0; j < 2; j++) \
                _Pragma("unroll") \
                for (int q = 0; q < 4; q++) dacc[mf][j][q] = 0.f; \
        _Pragma("unroll") \
        for (int ks = 0; ks < 4; ks++) { \
            const uint32_t kb = (uint32_t)(ks << 5); \
            uint32_t af[4][4], bf[4]; \
            _Pragma("unroll") \
            for (int mf = 0; mf < 4; mf++) \
                LDSM_X4(af[mf], a_base + a_off + (uint32_t)(mf * 16 * SLDH * 2) + kb); \
            LDSM_X4(bf, b_base + b_off + (uint32_t)(np * 16 * SLDH * 2) + kb); \
            _Pragma("unroll") \
            for (int mf = 0; mf < 4; mf++) \
                _Pragma("unroll") \
                for (int j = 0; j < 2; j++) \
                    mma_f16(dacc[mf][j], af[mf], bf + (j << 1)); \
        } \
        _Pragma("unroll") \
        for (int mf = 0; mf < 4; mf++) \
            _Pragma("unroll") \
            for (int j = 0; j < 2; j++) \
                _Pragma("unroll") \
                for (int q = 0; q < 4; q++) { \
                    if (is_add_) acc[mf][np * 2 + j][q] += dacc[mf][j][q]; \
                    else         acc[mf][np * 2 + j][q] *= dacc[mf][j][q]; \
                } \
    } \
} while (0)

    ISSUE_DY(0, 0);
    ISSUE_DY(1, 1);
    ISSUE_DY(2, 2);
    WAITG2();
    __syncthreads();
    DY_CHAIN(0, 0);          // acc *= dyh
    WAITG1();
    __syncthreads();
    DY_CHAIN(1, 0);          // acc *= dyx
    WAITG0();
    __syncthreads();
    DY_CHAIN(2, 1);          // acc += dyb
#undef ISSUE_DY
#undef DY_CHAIN

    // ---- epilogue: + bias, write f32 gates ----
    const int r0 = bM + wm + (lane >> 2);
    const int c0 = bN + wn + ((lane & 3) << 1);
#pragma unroll
    for (int mf = 0; mf < 4; mf++) {
#pragma unroll
        for (int half = 0; half < 2; half++) {
            const int row = r0 + mf * 16 + half * 8;
            float* Cf = g_gates + (size_t)row * 4096;
#pragma unroll
            for (int nf = 0; nf < 4; nf++) {
                const int col = c0 + nf * 8;
                float2 v;
                v.x = acc[mf][nf][half * 2 + 0] + bias[col];
                v.y = acc[mf][nf][half * 2 + 1] + bias[col + 1];
                *reinterpret_cast<float2*>(Cf + col) = v;
            }
        }
    }
}

// ---------------- elementwise cells ----------------
__global__ void hyper_cell(const float* __restrict__ chat0,
                           const float* __restrict__ hbias,
                           float* __restrict__ out_hhat1,
                           float* __restrict__ out_chat1) {
    int idx = blockIdx.x * blockDim.x + threadIdx.x;
    if (idx >= NB * NZ) return;
    int b = idx >> 8;
    int z = idx & (NZ - 1);
    const float* p0 = g_hgp + (size_t)b * 1024;
    const float* p1 = p0 + (size_t)NB * 1024;
    float iv = p0[z] + p1[z] + hbias[z];
    float gv = p0[NZ + z] + p1[NZ + z] + hbias[NZ + z];
    float fv = p0[2 * NZ + z] + p1[2 * NZ + z] + hbias[2 * NZ + z];
    float ov = p0[3 * NZ + z] + p1[3 * NZ + z] + hbias[3 * NZ + z];
    float c1 = sigf(fv) * chat0[idx] + sigf(iv) * tanhf(gv);
    float h1 = sigf(ov) * tanhf(c1);
    out_chat1[idx] = c1;
    out_hhat1[idx] = h1;
    g_hhat1h[idx] = __float2half_rn(h1);
}

__global__ void main_cell(const float* __restrict__ c0,
                          float* __restrict__ out_h1,
                          float* __restrict__ out_c1) {
    int idx = blockIdx.x * blockDim.x + threadIdx.x;
    if (idx >= NB * NH) return;
    int b = idx >> 10;
    int h = idx & (NH - 1);
    const float* row = g_gates + (size_t)b * (4 * NH);
    float iv = row[h], gv = row[NH + h], fv = row[2 * NH + h], ov = row[3 * NH + h];
    float c1 = sigf(fv) * c0[idx] + sigf(iv) * tanhf(gv);
    out_c1[idx] = c1;
    out_h1[idx] = sigf(ov) * tanhf(c1);
}

// ---------------- launch ----------------
extern "C" void kernel_launch(void* const* d_in, const int* in_sizes, int n_in,
                              void* d_out, int out_size) {
    const float* x       = (const float*)d_in[0];
    const float* h0      = (const float*)d_in[1];
    const float* c0      = (const float*)d_in[2];
    const float* hhat0   = (const float*)d_in[3];
    const float* chat0   = (const float*)d_in[4];
    const float* hweight = (const float*)d_in[5];
    const float* hbias   = (const float*)d_in[6];
    const float* zw_h    = (const float*)d_in[7];
    const float* zw_x    = (const float*)d_in[8];
    const float* zw_b    = (const float*)d_in[9];
    const float* zb_h    = (const float*)d_in[10];
    const float* zb_x    = (const float*)d_in[11];
    const float* dw_h    = (const float*)d_in[12];
    const float* dw_x    = (const float*)d_in[13];
    const float* dw_b    = (const float*)d_in[14];
    const float* weight  = (const float*)d_in[15];
    const float* bias    = (const float*)d_in[16];
    float* out = (float*)d_out;

    static int smem_set = 0;
    if (!smem_set) {
        cudaFuncSetAttribute(hyper_gemm, cudaFuncAttributeMaxDynamicSharedMemorySize, SMEM_TOT);
        cudaFuncSetAttribute(z_gemm, cudaFuncAttributeMaxDynamicSharedMemorySize, SMEM_TOT);
        cudaFuncSetAttribute(main_gemm, cudaFuncAttributeMaxDynamicSharedMemorySize, SMEM_TOT);
        smem_set = 1;
    }

    float* out_h1    = out;
    float* out_c1    = out + (size_t)NB * NH;
    float* out_hhat1 = out + (size_t)2 * NB * NH;
    float* out_chat1 = out + (size_t)2 * NB * NH + (size_t)NB * NZ;

    // 1. prep: concat + convert activations; transpose + convert weights
    prep_all<<<12480, 256>>>((const float4*)x, (const float4*)h0, (const float4*)hhat0,
                             zb_h, zb_x, hweight, weight, zw_h, zw_x, zw_b,
                             dw_h, dw_x, dw_b);

    // 2. hyper GEMM split-K=2: hg partials  [2048,1024], K=2x1152
    hyper_gemm<<<dim3(8, 16, 2), 256, SMEM_TOT>>>();

    // 3. hyper cell (sums partials + hbias)
    hyper_cell<<<(NB * NZ) / 256, 256>>>(chat0, hbias, out_hhat1, out_chat1);

    // 4. fused z GEMM: z = hhat1 @ zw_cat + zb_cat  [2048,768], K=256 (half out)
    z_gemm<<<dim3(6, 16), 256, SMEM_TOT>>>();

    // 5. main GEMM with fused modulation  [2048,4096], K=2048
    main_gemm<<<dim3(32, 16), 256, SMEM_TOT>>>(bias);

    // 6. main cell
    main_cell<<<(NB * NH) / 256, 256>>>(c0, out_h1, out_c1);
}